// round 2
// baseline (speedup 1.0000x reference)
#include <cuda_runtime.h>
#include <math.h>

#define D_MODEL 512
#define SEQ     4096
#define BATCH   2
#define NHEAD   8
#define DHEAD   64
#define DFF     2048
#define MROWS   (BATCH*SEQ)   // 8192

// ---------------- scratch (static device globals; no allocation) ----------------
__device__ float g_Q [MROWS*D_MODEL];
__device__ float g_K [MROWS*D_MODEL];
__device__ float g_V [MROWS*D_MODEL];
__device__ float g_O [MROWS*D_MODEL];
__device__ float g_T [MROWS*D_MODEL];
__device__ float g_X1[MROWS*D_MODEL];
__device__ float g_F [MROWS*DFF];

// ---------------- generic fp32 GEMM: C[M,N] = A[M,K] @ B[K,N] (+bias)(relu) ----
// 128x128 tile, BK=8, 256 threads, 8x8 per-thread microtile.
__global__ __launch_bounds__(256, 2)
void sgemm128(const float* __restrict__ A, const float* __restrict__ B,
              float* __restrict__ C, int M, int N, int K,
              const float* __restrict__ bias, int relu)
{
    __shared__ float As[8][132];   // [k][m], padded
    __shared__ float Bs[8][128];   // [k][n]

    const int tid = threadIdx.x;
    const int ty  = tid >> 4;      // 0..15
    const int tx  = tid & 15;      // 0..15

    const int aR = tid >> 1, aC = (tid & 1) << 2;   // A: 128 rows x 8k, float4 along k
    const int bR = tid >> 5, bC = (tid & 31) << 2;  // B: 8k x 128 cols, float4 along n

    const float* Ag = A + (size_t)(blockIdx.y * 128 + aR) * K + aC;
    const float* Bg = B + (size_t)bR * N + blockIdx.x * 128 + bC;

    float acc[8][8];
#pragma unroll
    for (int i = 0; i < 8; i++)
#pragma unroll
        for (int j = 0; j < 8; j++) acc[i][j] = 0.f;

    for (int k0 = 0; k0 < K; k0 += 8) {
        float4 av = *(const float4*)(Ag + k0);
        float4 bv = *(const float4*)(Bg + (size_t)k0 * N);
        __syncthreads();
        As[aC + 0][aR] = av.x;
        As[aC + 1][aR] = av.y;
        As[aC + 2][aR] = av.z;
        As[aC + 3][aR] = av.w;
        *(float4*)&Bs[bR][bC] = bv;
        __syncthreads();
#pragma unroll
        for (int kk = 0; kk < 8; kk++) {
            float a[8], b[8];
            *(float4*)&a[0] = *(const float4*)&As[kk][ty * 8];
            *(float4*)&a[4] = *(const float4*)&As[kk][ty * 8 + 4];
            *(float4*)&b[0] = *(const float4*)&Bs[kk][tx * 8];
            *(float4*)&b[4] = *(const float4*)&Bs[kk][tx * 8 + 4];
#pragma unroll
            for (int i = 0; i < 8; i++)
#pragma unroll
                for (int j = 0; j < 8; j++)
                    acc[i][j] = fmaf(a[i], b[j], acc[i][j]);
        }
    }

    float bb[8];
#pragma unroll
    for (int j = 0; j < 8; j++)
        bb[j] = bias ? bias[blockIdx.x * 128 + tx * 8 + j] : 0.f;

#pragma unroll
    for (int i = 0; i < 8; i++) {
        float* Cp = C + (size_t)(blockIdx.y * 128 + ty * 8 + i) * N
                      + blockIdx.x * 128 + tx * 8;
        float o[8];
#pragma unroll
        for (int j = 0; j < 8; j++) {
            float v = acc[i][j] + bb[j];
            o[j] = relu ? fmaxf(v, 0.f) : v;
        }
        *(float4*)Cp       = *(float4*)&o[0];
        *(float4*)(Cp + 4) = *(float4*)&o[4];
    }
}

// ---------------- fused sigmoid-attention --------------------------------------
// No softmax stats needed: O[q,:] = sum_k sigmoid(q.k/8 + bias) * V[k,:]
// Per CTA: one (b,h), one 128-query tile; stream 128-key tiles.
// smem: sQt[64][132] + sKt[64][132] + sV[128][64] + sS[128][132]  = 164 KB
#define SQT_P 132
#define SS_P  132

extern __shared__ float attn_smem[];

__global__ __launch_bounds__(256, 1)
void attn_sigmoid_kernel(const float* __restrict__ Q, const float* __restrict__ K,
                         const float* __restrict__ V, float* __restrict__ O,
                         float scale, float sbias)
{
    float* sQt = attn_smem;                 // [d][q] 64x132
    float* sKt = sQt + 64 * SQT_P;          // [d][k] 64x132
    float* sV  = sKt + 64 * SQT_P;          // [k][d] 128x64
    float* sS  = sV  + 128 * 64;            // [q][k] 128x132

    const int tid = threadIdx.x;
    const int qt  = blockIdx.x;             // 0..31
    const int bh  = blockIdx.y;             // 0..15
    const int b   = bh >> 3, h = bh & 7;
    const size_t baseRow = (size_t)b * SEQ;
    const int colBase = h * DHEAD;

    const int lr = tid >> 4;                // loader row 0..15
    const int lc = (tid & 15) << 2;         // loader col4 0..60

    // load Q tile transposed
#pragma unroll
    for (int i = 0; i < 8; i++) {
        int r = lr + i * 16;
        float4 v = *(const float4*)(Q + (baseRow + (size_t)qt * 128 + r) * D_MODEL + colBase + lc);
        sQt[(lc + 0) * SQT_P + r] = v.x;
        sQt[(lc + 1) * SQT_P + r] = v.y;
        sQt[(lc + 2) * SQT_P + r] = v.z;
        sQt[(lc + 3) * SQT_P + r] = v.w;
    }

    float oacc[4][8];
#pragma unroll
    for (int i = 0; i < 4; i++)
#pragma unroll
        for (int j = 0; j < 8; j++) oacc[i][j] = 0.f;

    const int sr = tid >> 4, sc = tid & 15;   // S-phase: 16x16 threads -> 8x8 each
    const int tr = tid >> 3, tc = tid & 7;    // O-phase: 32x8 threads -> 4x8 each

    for (int kt = 0; kt < SEQ / 128; kt++) {
        __syncthreads();   // prior O-phase done reading sV; also covers sQt stores at kt=0
        // load K tile (transposed) and V tile
#pragma unroll
        for (int i = 0; i < 8; i++) {
            int r = lr + i * 16;
            size_t grow = (baseRow + (size_t)kt * 128 + r) * D_MODEL + colBase + lc;
            float4 kv = *(const float4*)(K + grow);
            sKt[(lc + 0) * SQT_P + r] = kv.x;
            sKt[(lc + 1) * SQT_P + r] = kv.y;
            sKt[(lc + 2) * SQT_P + r] = kv.z;
            sKt[(lc + 3) * SQT_P + r] = kv.w;
            float4 vv = *(const float4*)(V + grow);
            *(float4*)&sV[r * 64 + lc] = vv;
        }
        __syncthreads();

        // S-phase: s = Q Kt (128x128x64)
        float s[8][8];
#pragma unroll
        for (int i = 0; i < 8; i++)
#pragma unroll
            for (int j = 0; j < 8; j++) s[i][j] = 0.f;

#pragma unroll
        for (int d = 0; d < 64; d++) {
            float a[8], bb[8];
            *(float4*)&a[0]  = *(const float4*)&sQt[d * SQT_P + sr * 8];
            *(float4*)&a[4]  = *(const float4*)&sQt[d * SQT_P + sr * 8 + 4];
            *(float4*)&bb[0] = *(const float4*)&sKt[d * SQT_P + sc * 8];
            *(float4*)&bb[4] = *(const float4*)&sKt[d * SQT_P + sc * 8 + 4];
#pragma unroll
            for (int i = 0; i < 8; i++)
#pragma unroll
                for (int j = 0; j < 8; j++)
                    s[i][j] = fmaf(a[i], bb[j], s[i][j]);
        }

        // sigmoid + stage to smem
#pragma unroll
        for (int i = 0; i < 8; i++) {
#pragma unroll
            for (int j = 0; j < 8; j++) {
                float xv = fmaf(s[i][j], scale, sbias);
                s[i][j] = 1.f / (1.f + __expf(-xv));
            }
            *(float4*)&sS[(sr * 8 + i) * SS_P + sc * 8]     = *(float4*)&s[i][0];
            *(float4*)&sS[(sr * 8 + i) * SS_P + sc * 8 + 4] = *(float4*)&s[i][4];
        }
        __syncthreads();

        // O-phase: O += S @ V (128x64x128)
#pragma unroll 4
        for (int k = 0; k < 128; k++) {
            float bb[8];
            *(float4*)&bb[0] = *(const float4*)&sV[k * 64 + tc * 8];
            *(float4*)&bb[4] = *(const float4*)&sV[k * 64 + tc * 8 + 4];
#pragma unroll
            for (int i = 0; i < 4; i++) {
                float a = sS[(tr * 4 + i) * SS_P + k];
#pragma unroll
                for (int j = 0; j < 8; j++)
                    oacc[i][j] = fmaf(a, bb[j], oacc[i][j]);
            }
        }
    }

    // write O tile (row-major [8192, 512], head slice)
#pragma unroll
    for (int i = 0; i < 4; i++) {
        size_t row = baseRow + (size_t)qt * 128 + tr * 4 + i;
        float* op = O + row * D_MODEL + colBase + tc * 8;
        *(float4*)op       = *(float4*)&oacc[i][0];
        *(float4*)(op + 4) = *(float4*)&oacc[i][4];
    }
}

// ---------------- residual + layernorm over 512 cols ---------------------------
__global__ __launch_bounds__(128)
void ln_res_kernel(const float* __restrict__ a, const float* __restrict__ t,
                   const float* __restrict__ gamma, const float* __restrict__ beta,
                   float* __restrict__ out)
{
    const int row = blockIdx.x;
    const int tid = threadIdx.x;      // 128 threads * 4 = 512
    const float4 va = ((const float4*)(a + (size_t)row * D_MODEL))[tid];
    const float4 vt = ((const float4*)(t + (size_t)row * D_MODEL))[tid];
    float v0 = va.x + vt.x, v1 = va.y + vt.y, v2 = va.z + vt.z, v3 = va.w + vt.w;

    float s  = v0 + v1 + v2 + v3;
    float ss = v0 * v0 + v1 * v1 + v2 * v2 + v3 * v3;
#pragma unroll
    for (int o = 16; o; o >>= 1) {
        s  += __shfl_xor_sync(0xffffffffu, s,  o);
        ss += __shfl_xor_sync(0xffffffffu, ss, o);
    }
    __shared__ float sh[8];
    if ((tid & 31) == 0) { sh[tid >> 5] = s; sh[4 + (tid >> 5)] = ss; }
    __syncthreads();
    float S2  = sh[0] + sh[1] + sh[2] + sh[3];
    float SS2 = sh[4] + sh[5] + sh[6] + sh[7];

    const float mu   = S2 * (1.f / 512.f);
    const float var  = SS2 * (1.f / 512.f) - mu * mu;
    const float rstd = rsqrtf(var + 1e-5f);

    const float4 g = ((const float4*)gamma)[tid];
    const float4 bb = ((const float4*)beta)[tid];
    float4 o;
    o.x = (v0 - mu) * rstd * g.x + bb.x;
    o.y = (v1 - mu) * rstd * g.y + bb.y;
    o.z = (v2 - mu) * rstd * g.z + bb.z;
    o.w = (v3 - mu) * rstd * g.w + bb.w;
    ((float4*)(out + (size_t)row * D_MODEL))[tid] = o;
}

// ---------------- launch --------------------------------------------------------
extern "C" void kernel_launch(void* const* d_in, const int* in_sizes, int n_in,
                              void* d_out, int out_size)
{
    const float* x       = (const float*)d_in[0];
    const float* Wq      = (const float*)d_in[1];
    const float* Wk      = (const float*)d_in[2];
    const float* Wv      = (const float*)d_in[3];
    const float* dense_w = (const float*)d_in[4];
    const float* dense_b = (const float*)d_in[5];
    const float* ff1_w   = (const float*)d_in[6];
    const float* ff1_b   = (const float*)d_in[7];
    const float* ff2_w   = (const float*)d_in[8];
    const float* ff2_b   = (const float*)d_in[9];
    const float* ln1_g   = (const float*)d_in[10];
    const float* ln1_b   = (const float*)d_in[11];
    const float* ln2_g   = (const float*)d_in[12];
    const float* ln2_b   = (const float*)d_in[13];

    float *Q, *K, *V, *O, *T, *X1, *F;
    cudaGetSymbolAddress((void**)&Q,  g_Q);
    cudaGetSymbolAddress((void**)&K,  g_K);
    cudaGetSymbolAddress((void**)&V,  g_V);
    cudaGetSymbolAddress((void**)&O,  g_O);
    cudaGetSymbolAddress((void**)&T,  g_T);
    cudaGetSymbolAddress((void**)&X1, g_X1);
    cudaGetSymbolAddress((void**)&F,  g_F);

    dim3 blk(256);
    dim3 g512(D_MODEL / 128, MROWS / 128);   // (4, 64)
    dim3 gff1(DFF / 128,     MROWS / 128);   // (16, 64)

    // Q,K,V projections
    sgemm128<<<g512, blk>>>(x, Wq, Q, MROWS, D_MODEL, D_MODEL, nullptr, 0);
    sgemm128<<<g512, blk>>>(x, Wk, K, MROWS, D_MODEL, D_MODEL, nullptr, 0);
    sgemm128<<<g512, blk>>>(x, Wv, V, MROWS, D_MODEL, D_MODEL, nullptr, 0);

    // fused sigmoid attention
    const size_t asmem = (size_t)(64 * SQT_P + 64 * SQT_P + 128 * 64 + 128 * SS_P) * sizeof(float);
    cudaFuncSetAttribute(attn_sigmoid_kernel,
                         cudaFuncAttributeMaxDynamicSharedMemorySize, (int)asmem);
    attn_sigmoid_kernel<<<dim3(SEQ / 128, BATCH * NHEAD), blk, asmem>>>(
        Q, K, V, O, 0.125f, -8.317766166719343f);  // 1/sqrt(64), -log(4096)

    // dense + residual LN1
    sgemm128<<<g512, blk>>>(O, dense_w, T, MROWS, D_MODEL, D_MODEL, dense_b, 0);
    ln_res_kernel<<<MROWS, 128>>>(x, T, ln1_g, ln1_b, X1);

    // FFN + residual LN2
    sgemm128<<<gff1, blk>>>(X1, ff1_w, F, MROWS, DFF, D_MODEL, ff1_b, 1);
    sgemm128<<<g512, blk>>>(F, ff2_w, T, MROWS, D_MODEL, DFF, ff2_b, 0);
    ln_res_kernel<<<MROWS, 128>>>(X1, T, ln2_g, ln2_b, (float*)d_out);
}

// round 5
// speedup vs baseline: 1.8712x; 1.8712x over previous
#include <cuda_runtime.h>
#include <math.h>

#define D_MODEL 512
#define SEQ     4096
#define BATCH   2
#define NHEAD   8
#define DHEAD   64
#define DFF     2048
#define MROWS   (BATCH*SEQ)   // 8192

// ---------------- scratch (static device globals; no allocation) ----------------
__device__ float g_Q [MROWS*D_MODEL];
__device__ float g_K [MROWS*D_MODEL];
__device__ float g_V [MROWS*D_MODEL];
__device__ float g_O [MROWS*D_MODEL];
__device__ float g_T [MROWS*D_MODEL];
__device__ float g_X1[MROWS*D_MODEL];
__device__ float g_F [MROWS*DFF];

// ---------------- tf32 helpers ---------------------------------------------------
__device__ __forceinline__ unsigned f2tf32(float x) {
    unsigned u;
    asm("cvt.rna.tf32.f32 %0, %1;" : "=r"(u) : "f"(x));
    return u;
}

// D += A@B, m16n8k8, A row-major, B col-major (i.e. B[k][n] smem layout)
#define MMA_TF32(d, a, b) \
    asm volatile("mma.sync.aligned.m16n8k8.row.col.f32.tf32.tf32.f32 " \
                 "{%0,%1,%2,%3},{%4,%5,%6,%7},{%8,%9},{%0,%1,%2,%3};" \
                 : "+f"((d)[0]), "+f"((d)[1]), "+f"((d)[2]), "+f"((d)[3]) \
                 : "r"((a)[0]), "r"((a)[1]), "r"((a)[2]), "r"((a)[3]), \
                   "r"((b)[0]), "r"((b)[1]))

// ---------------- tf32 tensor-core GEMM: C[M,N] = A[M,K]@B[K,N] (+bias)(relu) ----
// 128x128 tile, BK=16, 256 threads = 8 warps (4m x 2n), warp tile 32x64.
// smem strides 136 words (== 8 mod 32) -> conflict-free fragment loads.
#define GAS 136
#define GBS 136

__global__ __launch_bounds__(256, 2)
void tgemm128(const float* __restrict__ A, const float* __restrict__ B,
              float* __restrict__ C, int M, int N, int K,
              const float* __restrict__ bias, int relu)
{
    __shared__ unsigned As_[2][16 * GAS];   // [k][m] tf32 bits
    __shared__ unsigned Bs_[2][16 * GBS];   // [k][n] tf32 bits

    const int tid  = threadIdx.x;
    const int warp = tid >> 5;
    const int lane = tid & 31;
    const int r    = lane >> 2;   // group id
    const int c    = lane & 3;    // thread-in-group

    const int wm = (warp & 3) * 32;   // warp m offset
    const int wn = (warp >> 2) * 64;  // warp n offset

    // global load mapping
    const int aRow = tid >> 1, aK0 = (tid & 1) * 8;          // A: 128 rows x 16k
    const int bRow = tid >> 4, bCol = (tid & 15) * 8;        // B: 16k x 128n

    const float* Ag = A + (size_t)(blockIdx.y * 128 + aRow) * K + aK0;
    const float* Bg = B + (size_t)bRow * N + blockIdx.x * 128 + bCol;

    float acc[2][8][4];
#pragma unroll
    for (int mt = 0; mt < 2; mt++)
#pragma unroll
        for (int nt = 0; nt < 8; nt++)
#pragma unroll
            for (int l = 0; l < 4; l++) acc[mt][nt][l] = 0.f;

    const int T = K >> 4;

    // preload tile 0
    {
        float av[8], bv[8];
        *(float4*)&av[0] = *(const float4*)(Ag);
        *(float4*)&av[4] = *(const float4*)(Ag + 4);
        *(float4*)&bv[0] = *(const float4*)(Bg);
        *(float4*)&bv[4] = *(const float4*)(Bg + 4);
#pragma unroll
        for (int j = 0; j < 8; j++) {
            As_[0][(aK0 + j) * GAS + aRow] = f2tf32(av[j]);
            Bs_[0][bRow * GBS + bCol + j]  = f2tf32(bv[j]);
        }
    }
    __syncthreads();

    for (int t = 0; t < T; t++) {
        const int buf = t & 1;
        float an[8], bn[8];
        if (t + 1 < T) {
            const float* Agn = Ag + (t + 1) * 16;
            const float* Bgn = Bg + (size_t)(t + 1) * 16 * N;
            *(float4*)&an[0] = *(const float4*)(Agn);
            *(float4*)&an[4] = *(const float4*)(Agn + 4);
            *(float4*)&bn[0] = *(const float4*)(Bgn);
            *(float4*)&bn[4] = *(const float4*)(Bgn + 4);
        }

        const unsigned* As = As_[buf];
        const unsigned* Bs = Bs_[buf];
#pragma unroll
        for (int ks = 0; ks < 16; ks += 8) {
            unsigned af[2][4];
#pragma unroll
            for (int mt = 0; mt < 2; mt++) {
                const int mb = wm + mt * 16;
                af[mt][0] = As[(ks + c) * GAS     + mb + r];
                af[mt][1] = As[(ks + c) * GAS     + mb + r + 8];
                af[mt][2] = As[(ks + c + 4) * GAS + mb + r];
                af[mt][3] = As[(ks + c + 4) * GAS + mb + r + 8];
            }
            unsigned bf[8][2];
#pragma unroll
            for (int nt = 0; nt < 8; nt++) {
                const int nb = wn + nt * 8 + r;
                bf[nt][0] = Bs[(ks + c) * GBS     + nb];
                bf[nt][1] = Bs[(ks + c + 4) * GBS + nb];
            }
#pragma unroll
            for (int mt = 0; mt < 2; mt++)
#pragma unroll
                for (int nt = 0; nt < 8; nt++)
                    MMA_TF32(acc[mt][nt], af[mt], bf[nt]);
        }

        if (t + 1 < T) {
            unsigned* Aw = As_[buf ^ 1];
            unsigned* Bw = Bs_[buf ^ 1];
#pragma unroll
            for (int j = 0; j < 8; j++) {
                Aw[(aK0 + j) * GAS + aRow] = f2tf32(an[j]);
                Bw[bRow * GBS + bCol + j]  = f2tf32(bn[j]);
            }
        }
        __syncthreads();
    }

    // epilogue: c0,c1 at (r, 2c),(r,2c+1); c2,c3 at (r+8, ...)
#pragma unroll
    for (int mt = 0; mt < 2; mt++) {
#pragma unroll
        for (int l2 = 0; l2 < 2; l2++) {
            const int row = blockIdx.y * 128 + wm + mt * 16 + r + 8 * l2;
#pragma unroll
            for (int nt = 0; nt < 8; nt++) {
                const int col = blockIdx.x * 128 + wn + nt * 8 + 2 * c;
                float v0 = acc[mt][nt][2 * l2 + 0];
                float v1 = acc[mt][nt][2 * l2 + 1];
                if (bias) { v0 += bias[col]; v1 += bias[col + 1]; }
                if (relu) { v0 = fmaxf(v0, 0.f); v1 = fmaxf(v1, 0.f); }
                float2 o = make_float2(v0, v1);
                *(float2*)(C + (size_t)row * N + col) = o;
            }
        }
    }
}

// ---------------- fused sigmoid-attention on tensor cores ------------------------
// O[q,:] = sum_k sigmoid(q.k/8 + bias) * V[k,:]  (no softmax stats)
// Per CTA: one (b,h), 128-query tile, stream 128-key tiles.
// smem (tf32 bits): Qs[d][q] 64x136, Ks[d][kk] 64x136, Vs[kk][d] 128x72,
//                   sS[q][kk] 128x136  -> 172 KB dynamic.
#define AQS 136
#define AKS 136
#define AVS 72
#define ASS 136

extern __shared__ unsigned attn_smem_u[];

__global__ __launch_bounds__(256, 1)
void attn_tc_kernel(const float* __restrict__ Q, const float* __restrict__ K,
                    const float* __restrict__ V, float* __restrict__ O,
                    float scale, float sbias)
{
    unsigned* Qs = attn_smem_u;               // 64*136
    unsigned* Ks = Qs + 64 * AQS;             // 64*136
    unsigned* Vs = Ks + 64 * AKS;             // 128*72
    unsigned* sS = Vs + 128 * AVS;            // 128*136

    const int tid  = threadIdx.x;
    const int warp = tid >> 5;
    const int lane = tid & 31;
    const int r    = lane >> 2;
    const int c    = lane & 3;

    const int wm = (warp & 3) * 32;           // q block (S & O phases)
    const int wnS = (warp >> 2) * 64;         // key block (S phase)
    const int wnO = (warp >> 2) * 32;         // d block  (O phase)

    const int qt = blockIdx.x;                // 0..31
    const int bh = blockIdx.y;                // 0..15
    const int b  = bh >> 3, h = bh & 7;
    const size_t baseRow = (size_t)b * SEQ;
    const int colBase = h * DHEAD;

    // loader: 128 rows x 64 cols, 256 threads: row=tid>>1, half=(tid&1)*32
    const int lrow = tid >> 1;
    const int ld0  = (tid & 1) * 32;

    // load+transpose Q tile -> Qs[d][q]
    {
        const float* Qg = Q + (baseRow + (size_t)qt * 128 + lrow) * D_MODEL + colBase + ld0;
#pragma unroll
        for (int g = 0; g < 8; g++) {
            float4 v = *(const float4*)(Qg + 4 * g);
            Qs[(ld0 + 4 * g + 0) * AQS + lrow] = f2tf32(v.x);
            Qs[(ld0 + 4 * g + 1) * AQS + lrow] = f2tf32(v.y);
            Qs[(ld0 + 4 * g + 2) * AQS + lrow] = f2tf32(v.z);
            Qs[(ld0 + 4 * g + 3) * AQS + lrow] = f2tf32(v.w);
        }
    }

    float oacc[2][4][4];
#pragma unroll
    for (int mt = 0; mt < 2; mt++)
#pragma unroll
        for (int nt = 0; nt < 4; nt++)
#pragma unroll
            for (int l = 0; l < 4; l++) oacc[mt][nt][l] = 0.f;

    for (int kt = 0; kt < SEQ / 128; kt++) {
        __syncthreads();   // prev O-phase done with Vs/sS; Qs ready at kt=0
        // load K (transposed) and V tiles
        {
            const size_t grow = (baseRow + (size_t)kt * 128 + lrow) * D_MODEL + colBase + ld0;
            const float* Kg = K + grow;
            const float* Vg = V + grow;
#pragma unroll
            for (int g = 0; g < 8; g++) {
                float4 kv = *(const float4*)(Kg + 4 * g);
                Ks[(ld0 + 4 * g + 0) * AKS + lrow] = f2tf32(kv.x);
                Ks[(ld0 + 4 * g + 1) * AKS + lrow] = f2tf32(kv.y);
                Ks[(ld0 + 4 * g + 2) * AKS + lrow] = f2tf32(kv.z);
                Ks[(ld0 + 4 * g + 3) * AKS + lrow] = f2tf32(kv.w);
                float4 vv = *(const float4*)(Vg + 4 * g);
                uint4 p;
                p.x = f2tf32(vv.x); p.y = f2tf32(vv.y);
                p.z = f2tf32(vv.z); p.w = f2tf32(vv.w);
                *(uint4*)&Vs[lrow * AVS + ld0 + 4 * g] = p;
            }
        }
        __syncthreads();

        // ---- S-phase: S = Q @ K^T  (M=128 q, N=128 kk, K=64 d) ----
        float sacc[2][8][4];
#pragma unroll
        for (int mt = 0; mt < 2; mt++)
#pragma unroll
            for (int nt = 0; nt < 8; nt++)
#pragma unroll
                for (int l = 0; l < 4; l++) sacc[mt][nt][l] = 0.f;

#pragma unroll
        for (int ks = 0; ks < 64; ks += 8) {
            unsigned af[2][4];
#pragma unroll
            for (int mt = 0; mt < 2; mt++) {
                const int mb = wm + mt * 16;
                af[mt][0] = Qs[(ks + c) * AQS     + mb + r];
                af[mt][1] = Qs[(ks + c) * AQS     + mb + r + 8];
                af[mt][2] = Qs[(ks + c + 4) * AQS + mb + r];
                af[mt][3] = Qs[(ks + c + 4) * AQS + mb + r + 8];
            }
            unsigned bf[8][2];
#pragma unroll
            for (int nt = 0; nt < 8; nt++) {
                const int nb = wnS + nt * 8 + r;
                bf[nt][0] = Ks[(ks + c) * AKS     + nb];
                bf[nt][1] = Ks[(ks + c + 4) * AKS + nb];
            }
#pragma unroll
            for (int mt = 0; mt < 2; mt++)
#pragma unroll
                for (int nt = 0; nt < 8; nt++)
                    MMA_TF32(sacc[mt][nt], af[mt], bf[nt]);
        }

        // sigmoid in regs, stage tf32 S -> sS[q][kk]
#pragma unroll
        for (int mt = 0; mt < 2; mt++)
#pragma unroll
            for (int nt = 0; nt < 8; nt++)
#pragma unroll
                for (int l = 0; l < 4; l++) {
                    float xv = fmaf(sacc[mt][nt][l], scale, sbias);
                    float sg = 1.f / (1.f + __expf(-xv));
                    const int q  = wm + mt * 16 + r + 8 * (l >> 1);
                    const int kk = wnS + nt * 8 + 2 * c + (l & 1);
                    sS[q * ASS + kk] = f2tf32(sg);
                }
        __syncthreads();

        // ---- O-phase: O += S @ V  (M=128 q, N=64 d, K=128 kk) ----
#pragma unroll 4
        for (int ks = 0; ks < 128; ks += 8) {
            unsigned af[2][4];
#pragma unroll
            for (int mt = 0; mt < 2; mt++) {
                const int mb = wm + mt * 16;
                af[mt][0] = sS[(mb + r) * ASS     + ks + c];
                af[mt][1] = sS[(mb + r + 8) * ASS + ks + c];
                af[mt][2] = sS[(mb + r) * ASS     + ks + c + 4];
                af[mt][3] = sS[(mb + r + 8) * ASS + ks + c + 4];
            }
            unsigned bf[4][2];
#pragma unroll
            for (int nt = 0; nt < 4; nt++) {
                const int nb = wnO + nt * 8 + r;
                bf[nt][0] = Vs[(ks + c) * AVS     + nb];
                bf[nt][1] = Vs[(ks + c + 4) * AVS + nb];
            }
#pragma unroll
            for (int mt = 0; mt < 2; mt++)
#pragma unroll
                for (int nt = 0; nt < 4; nt++)
                    MMA_TF32(oacc[mt][nt], af[mt], bf[nt]);
        }
    }

    // write O tile
#pragma unroll
    for (int mt = 0; mt < 2; mt++) {
#pragma unroll
        for (int l2 = 0; l2 < 2; l2++) {
            const size_t row = baseRow + (size_t)qt * 128 + wm + mt * 16 + r + 8 * l2;
#pragma unroll
            for (int nt = 0; nt < 4; nt++) {
                const int col = colBase + wnO + nt * 8 + 2 * c;
                float2 o = make_float2(oacc[mt][nt][2 * l2 + 0],
                                       oacc[mt][nt][2 * l2 + 1]);
                *(float2*)(O + row * D_MODEL + col) = o;
            }
        }
    }
}

// ---------------- residual + layernorm over 512 cols ---------------------------
__global__ __launch_bounds__(128)
void ln_res_kernel(const float* __restrict__ a, const float* __restrict__ t,
                   const float* __restrict__ gamma, const float* __restrict__ beta,
                   float* __restrict__ out)
{
    const int row = blockIdx.x;
    const int tid = threadIdx.x;      // 128 threads * 4 = 512
    const float4 va = ((const float4*)(a + (size_t)row * D_MODEL))[tid];
    const float4 vt = ((const float4*)(t + (size_t)row * D_MODEL))[tid];
    float v0 = va.x + vt.x, v1 = va.y + vt.y, v2 = va.z + vt.z, v3 = va.w + vt.w;

    float s  = v0 + v1 + v2 + v3;
    float ss = v0 * v0 + v1 * v1 + v2 * v2 + v3 * v3;
#pragma unroll
    for (int o = 16; o; o >>= 1) {
        s  += __shfl_xor_sync(0xffffffffu, s,  o);
        ss += __shfl_xor_sync(0xffffffffu, ss, o);
    }
    __shared__ float sh[8];
    if ((tid & 31) == 0) { sh[tid >> 5] = s; sh[4 + (tid >> 5)] = ss; }
    __syncthreads();
    float S2  = sh[0] + sh[1] + sh[2] + sh[3];
    float SS2 = sh[4] + sh[5] + sh[6] + sh[7];

    const float mu   = S2 * (1.f / 512.f);
    const float var  = SS2 * (1.f / 512.f) - mu * mu;
    const float rstd = rsqrtf(var + 1e-5f);

    const float4 g  = ((const float4*)gamma)[tid];
    const float4 bb = ((const float4*)beta)[tid];
    float4 o;
    o.x = (v0 - mu) * rstd * g.x + bb.x;
    o.y = (v1 - mu) * rstd * g.y + bb.y;
    o.z = (v2 - mu) * rstd * g.z + bb.z;
    o.w = (v3 - mu) * rstd * g.w + bb.w;
    ((float4*)(out + (size_t)row * D_MODEL))[tid] = o;
}

// ---------------- launch --------------------------------------------------------
extern "C" void kernel_launch(void* const* d_in, const int* in_sizes, int n_in,
                              void* d_out, int out_size)
{
    const float* x       = (const float*)d_in[0];
    const float* Wq      = (const float*)d_in[1];
    const float* Wk      = (const float*)d_in[2];
    const float* Wv      = (const float*)d_in[3];
    const float* dense_w = (const float*)d_in[4];
    const float* dense_b = (const float*)d_in[5];
    const float* ff1_w   = (const float*)d_in[6];
    const float* ff1_b   = (const float*)d_in[7];
    const float* ff2_w   = (const float*)d_in[8];
    const float* ff2_b   = (const float*)d_in[9];
    const float* ln1_g   = (const float*)d_in[10];
    const float* ln1_b   = (const float*)d_in[11];
    const float* ln2_g   = (const float*)d_in[12];
    const float* ln2_b   = (const float*)d_in[13];

    float *Q, *K, *V, *O, *T, *X1, *F;
    cudaGetSymbolAddress((void**)&Q,  g_Q);
    cudaGetSymbolAddress((void**)&K,  g_K);
    cudaGetSymbolAddress((void**)&V,  g_V);
    cudaGetSymbolAddress((void**)&O,  g_O);
    cudaGetSymbolAddress((void**)&T,  g_T);
    cudaGetSymbolAddress((void**)&X1, g_X1);
    cudaGetSymbolAddress((void**)&F,  g_F);

    dim3 blk(256);
    dim3 g512(D_MODEL / 128, MROWS / 128);   // (4, 64)
    dim3 gff1(DFF / 128,     MROWS / 128);   // (16, 64)

    // Q,K,V projections (tf32 tensor cores)
    tgemm128<<<g512, blk>>>(x, Wq, Q, MROWS, D_MODEL, D_MODEL, nullptr, 0);
    tgemm128<<<g512, blk>>>(x, Wk, K, MROWS, D_MODEL, D_MODEL, nullptr, 0);
    tgemm128<<<g512, blk>>>(x, Wv, V, MROWS, D_MODEL, D_MODEL, nullptr, 0);

    // fused sigmoid attention (tf32 tensor cores)
    const size_t asmem = (size_t)(64 * AQS + 64 * AKS + 128 * AVS + 128 * ASS) * sizeof(unsigned);
    cudaFuncSetAttribute(attn_tc_kernel,
                         cudaFuncAttributeMaxDynamicSharedMemorySize, (int)asmem);
    attn_tc_kernel<<<dim3(SEQ / 128, BATCH * NHEAD), blk, asmem>>>(
        Q, K, V, O, 0.125f, -8.317766166719343f);  // 1/sqrt(64), -log(4096)

    // dense + residual LN1
    tgemm128<<<g512, blk>>>(O, dense_w, T, MROWS, D_MODEL, D_MODEL, dense_b, 0);
    ln_res_kernel<<<MROWS, 128>>>(x, T, ln1_g, ln1_b, X1);

    // FFN + residual LN2
    tgemm128<<<gff1, blk>>>(X1, ff1_w, F, MROWS, DFF, D_MODEL, ff1_b, 1);
    tgemm128<<<g512, blk>>>(F, ff2_w, T, MROWS, D_MODEL, DFF, ff2_b, 0);
    ln_res_kernel<<<MROWS, 128>>>(X1, T, ln2_g, ln2_b, (float*)d_out);
}

// round 6
// speedup vs baseline: 2.4852x; 1.3282x over previous
#include <cuda_runtime.h>
#include <math.h>

#define D_MODEL 512
#define SEQ     4096
#define BATCH   2
#define NHEAD   8
#define DHEAD   64
#define DFF     2048
#define MROWS   (BATCH*SEQ)   // 8192

// ---------------- scratch (static device globals; no allocation) ----------------
__device__ float g_Q [MROWS*D_MODEL];
__device__ float g_K [MROWS*D_MODEL];
__device__ float g_V [MROWS*D_MODEL];
__device__ float g_O [MROWS*D_MODEL];
__device__ float g_T [MROWS*D_MODEL];
__device__ float g_X1[MROWS*D_MODEL];
__device__ float g_F [MROWS*DFF];

// ---------------- tf32 helpers ---------------------------------------------------
__device__ __forceinline__ unsigned f2tf32(float x) {
    unsigned u;
    asm("cvt.rna.tf32.f32 %0, %1;" : "=r"(u) : "f"(x));
    return u;
}

// D += A@B, m16n8k8, A row-major, B col-major
#define MMA_TF32(d, a, b) \
    asm volatile("mma.sync.aligned.m16n8k8.row.col.f32.tf32.tf32.f32 " \
                 "{%0,%1,%2,%3},{%4,%5,%6,%7},{%8,%9},{%0,%1,%2,%3};" \
                 : "+f"((d)[0]), "+f"((d)[1]), "+f"((d)[2]), "+f"((d)[3]) \
                 : "r"((a)[0]), "r"((a)[1]), "r"((a)[2]), "r"((a)[3]), \
                   "r"((b)[0]), "r"((b)[1]))

// ================= tf32 GEMM body: C[M,N] = A[M,K]@B[K,N] (+bias)(relu) =========
// 128x128 tile, BK=16, 256 threads = 8 warps (4m x 2n), warp tile 32x64.
// K-minor smem layouts, stride 20 words: As[m][k], Bs[n][k].
// B-frag bank = (20r+c) mod 32 : 32 distinct -> conflict-free.
// A-frag bank = (20r+c) mod 32 : conflict-free.
#define GST 20

__device__ __forceinline__
void gemm_body(const float* __restrict__ A, const float* __restrict__ B,
               float* __restrict__ C, int N, int K,
               const float* __restrict__ bias, int relu,
               int bx, int by, unsigned* As_, unsigned* Bs_)
{
    const int tid  = threadIdx.x;
    const int warp = tid >> 5;
    const int lane = tid & 31;
    const int r    = lane >> 2;
    const int c    = lane & 3;

    const int wm = (warp & 3) * 32;
    const int wn = (warp >> 2) * 64;

    // A loader: row-major, aRow fine
    const int aRow = tid >> 1, aK0 = (tid & 1) * 8;
    // B loader: fine-k mapping for transpose store
    const int bK = tid & 15, bN0 = (tid >> 4) * 8;

    const float* Ag = A + (size_t)(by * 128 + aRow) * K + aK0;
    const float* Bg = B + (size_t)bK * N + bx * 128 + bN0;

    float acc[2][8][4];
#pragma unroll
    for (int mt = 0; mt < 2; mt++)
#pragma unroll
        for (int nt = 0; nt < 8; nt++)
#pragma unroll
            for (int l = 0; l < 4; l++) acc[mt][nt][l] = 0.f;

    const int T = K >> 4;

    // preload tile 0
    {
        float av[8], bv[8];
        *(float4*)&av[0] = *(const float4*)(Ag);
        *(float4*)&av[4] = *(const float4*)(Ag + 4);
        *(float4*)&bv[0] = *(const float4*)(Bg);
        *(float4*)&bv[4] = *(const float4*)(Bg + 4);
        uint4 pa0, pa1;
        pa0.x = f2tf32(av[0]); pa0.y = f2tf32(av[1]); pa0.z = f2tf32(av[2]); pa0.w = f2tf32(av[3]);
        pa1.x = f2tf32(av[4]); pa1.y = f2tf32(av[5]); pa1.z = f2tf32(av[6]); pa1.w = f2tf32(av[7]);
        *(uint4*)&As_[0 + aRow * GST + aK0]     = pa0;
        *(uint4*)&As_[0 + aRow * GST + aK0 + 4] = pa1;
#pragma unroll
        for (int j = 0; j < 8; j++)
            Bs_[0 + (bN0 + j) * GST + bK] = f2tf32(bv[j]);
    }
    __syncthreads();

    for (int t = 0; t < T; t++) {
        const int buf = (t & 1) * 128 * GST;
        float an[8], bn[8];
        if (t + 1 < T) {
            const float* Agn = Ag + (t + 1) * 16;
            const float* Bgn = Bg + (size_t)(t + 1) * 16 * N;
            *(float4*)&an[0] = *(const float4*)(Agn);
            *(float4*)&an[4] = *(const float4*)(Agn + 4);
            *(float4*)&bn[0] = *(const float4*)(Bgn);
            *(float4*)&bn[4] = *(const float4*)(Bgn + 4);
        }

        const unsigned* As = As_ + buf;
        const unsigned* Bs = Bs_ + buf;
#pragma unroll
        for (int ks = 0; ks < 16; ks += 8) {
            unsigned af[2][4];
#pragma unroll
            for (int mt = 0; mt < 2; mt++) {
                const int mb = wm + mt * 16;
                af[mt][0] = As[(mb + r) * GST     + ks + c];
                af[mt][1] = As[(mb + r + 8) * GST + ks + c];
                af[mt][2] = As[(mb + r) * GST     + ks + c + 4];
                af[mt][3] = As[(mb + r + 8) * GST + ks + c + 4];
            }
#pragma unroll
            for (int nt = 0; nt < 8; nt++) {
                unsigned bf[2];
                const int nb = wn + nt * 8 + r;
                bf[0] = Bs[nb * GST + ks + c];
                bf[1] = Bs[nb * GST + ks + c + 4];
#pragma unroll
                for (int mt = 0; mt < 2; mt++)
                    MMA_TF32(acc[mt][nt], af[mt], bf);
            }
        }

        if (t + 1 < T) {
            unsigned* Aw = As_ + (buf ^ (128 * GST));
            unsigned* Bw = Bs_ + (buf ^ (128 * GST));
            uint4 pa0, pa1;
            pa0.x = f2tf32(an[0]); pa0.y = f2tf32(an[1]); pa0.z = f2tf32(an[2]); pa0.w = f2tf32(an[3]);
            pa1.x = f2tf32(an[4]); pa1.y = f2tf32(an[5]); pa1.z = f2tf32(an[6]); pa1.w = f2tf32(an[7]);
            *(uint4*)&Aw[aRow * GST + aK0]     = pa0;
            *(uint4*)&Aw[aRow * GST + aK0 + 4] = pa1;
#pragma unroll
            for (int j = 0; j < 8; j++)
                Bw[(bN0 + j) * GST + bK] = f2tf32(bn[j]);
        }
        __syncthreads();
    }

    // epilogue
#pragma unroll
    for (int mt = 0; mt < 2; mt++) {
#pragma unroll
        for (int l2 = 0; l2 < 2; l2++) {
            const int row = by * 128 + wm + mt * 16 + r + 8 * l2;
#pragma unroll
            for (int nt = 0; nt < 8; nt++) {
                const int col = bx * 128 + wn + nt * 8 + 2 * c;
                float v0 = acc[mt][nt][2 * l2 + 0];
                float v1 = acc[mt][nt][2 * l2 + 1];
                if (bias) { v0 += bias[col]; v1 += bias[col + 1]; }
                if (relu) { v0 = fmaxf(v0, 0.f); v1 = fmaxf(v1, 0.f); }
                *(float2*)(C + (size_t)row * N + col) = make_float2(v0, v1);
            }
        }
    }
}

__global__ __launch_bounds__(256, 2)
void tgemm(const float* __restrict__ A, const float* __restrict__ B,
           float* __restrict__ C, int N, int K,
           const float* __restrict__ bias, int relu)
{
    __shared__ unsigned As_[2 * 128 * GST];
    __shared__ unsigned Bs_[2 * 128 * GST];
    gemm_body(A, B, C, N, K, bias, relu, blockIdx.x, blockIdx.y, As_, Bs_);
}

__global__ __launch_bounds__(256, 2)
void tgemm_qkv(const float* __restrict__ A,
               const float* __restrict__ Wq, const float* __restrict__ Wk,
               const float* __restrict__ Wv,
               float* __restrict__ Q, float* __restrict__ K,
               float* __restrict__ V)
{
    __shared__ unsigned As_[2 * 128 * GST];
    __shared__ unsigned Bs_[2 * 128 * GST];
    const float* B = (blockIdx.z == 0) ? Wq : (blockIdx.z == 1) ? Wk : Wv;
    float*       C = (blockIdx.z == 0) ? Q  : (blockIdx.z == 1) ? K  : V;
    gemm_body(A, B, C, D_MODEL, D_MODEL, nullptr, 0, blockIdx.x, blockIdx.y, As_, Bs_);
}

// ================= fused sigmoid-attention, tensor cores, no S staging ==========
// O[q,:] = sum_k sigmoid(q.k*scale + bias) * V[k,:]
// CTA: 256 thr (8 warps), q-tile 128 (16 q/warp), k-tile 64, 2 CTAs/SM.
// smem: Qs[q][d] 128x68, Ks[kk][d] 64x68, Vs[d][kk] 64x68  (tf32 bits) = 68KB.
// S stays in registers; O-phase A-frag built by warp shuffle transpose.
#define ATS 68

extern __shared__ unsigned attn_sm[];

__global__ __launch_bounds__(256, 2)
void attn_tc2(const float* __restrict__ Q, const float* __restrict__ K,
              const float* __restrict__ V, float* __restrict__ O,
              float scale, float sbias)
{
    unsigned* Qs = attn_sm;               // 128*68
    unsigned* Ks = Qs + 128 * ATS;        // 64*68
    unsigned* Vs = Ks + 64 * ATS;         // 64*68  (Vs[d*68 + kk])

    const int tid  = threadIdx.x;
    const int warp = tid >> 5;
    const int lane = tid & 31;
    const int r    = lane >> 2;
    const int c    = lane & 3;
    const int q0   = warp * 16;

    const int qt = blockIdx.x;            // 0..31
    const int bh = blockIdx.y;            // 0..15
    const int b  = bh >> 3, h = bh & 7;
    const size_t baseRow = (size_t)b * SEQ;
    const int colBase = h * DHEAD;

    // ---- load Q tile: Qs[q][d], stride 68 ----
    {
        const int qr = tid >> 1, d0 = (tid & 1) * 32;
        const float* Qg = Q + (baseRow + (size_t)qt * 128 + qr) * D_MODEL + colBase + d0;
#pragma unroll
        for (int g = 0; g < 8; g++) {
            float4 v = *(const float4*)(Qg + 4 * g);
            uint4 p;
            p.x = f2tf32(v.x); p.y = f2tf32(v.y); p.z = f2tf32(v.z); p.w = f2tf32(v.w);
            *(uint4*)&Qs[qr * ATS + d0 + 4 * g] = p;
        }
    }

    float oacc[8][4];
#pragma unroll
    for (int nt = 0; nt < 8; nt++)
#pragma unroll
        for (int l = 0; l < 4; l++) oacc[nt][l] = 0.f;

    const int kr  = tid >> 2, kd0 = (tid & 3) * 16;   // K loader
    const int vk  = tid & 63, vd0 = (tid >> 6) * 16;  // V loader (transpose)

    const int srcA = (lane & ~3) | (c >> 1);
    const int srcB = srcA | 2;
    const bool odd = (c & 1);

    for (int kt = 0; kt < SEQ / 64; kt++) {
        __syncthreads();   // prior compute done reading Ks/Vs (covers Qs at kt=0)
        // K tile: Ks[kk][d]
        {
            const float* Kg = K + (baseRow + (size_t)kt * 64 + kr) * D_MODEL + colBase + kd0;
#pragma unroll
            for (int g = 0; g < 4; g++) {
                float4 v = *(const float4*)(Kg + 4 * g);
                uint4 p;
                p.x = f2tf32(v.x); p.y = f2tf32(v.y); p.z = f2tf32(v.z); p.w = f2tf32(v.w);
                *(uint4*)&Ks[kr * ATS + kd0 + 4 * g] = p;
            }
        }
        // V tile transposed: Vs[d][kk]
        {
            const float* Vg = V + (baseRow + (size_t)kt * 64 + vk) * D_MODEL + colBase + vd0;
#pragma unroll
            for (int g = 0; g < 4; g++) {
                float4 v = *(const float4*)(Vg + 4 * g);
                Vs[(vd0 + 4 * g + 0) * ATS + vk] = f2tf32(v.x);
                Vs[(vd0 + 4 * g + 1) * ATS + vk] = f2tf32(v.y);
                Vs[(vd0 + 4 * g + 2) * ATS + vk] = f2tf32(v.z);
                Vs[(vd0 + 4 * g + 3) * ATS + vk] = f2tf32(v.w);
            }
        }
        __syncthreads();

        // ---- S-phase: S[16q x 64k] = Q @ K^T, accum in regs ----
        float sacc[8][4];
#pragma unroll
        for (int nt = 0; nt < 8; nt++)
#pragma unroll
            for (int l = 0; l < 4; l++) sacc[nt][l] = 0.f;

#pragma unroll
        for (int ks = 0; ks < 64; ks += 8) {
            unsigned af[4];
            af[0] = Qs[(q0 + r) * ATS     + ks + c];
            af[1] = Qs[(q0 + r + 8) * ATS + ks + c];
            af[2] = Qs[(q0 + r) * ATS     + ks + c + 4];
            af[3] = Qs[(q0 + r + 8) * ATS + ks + c + 4];
#pragma unroll
            for (int nt = 0; nt < 8; nt++) {
                unsigned bf[2];
                bf[0] = Ks[(nt * 8 + r) * ATS + ks + c];
                bf[1] = Ks[(nt * 8 + r) * ATS + ks + c + 4];
                MMA_TF32(sacc[nt], af, bf);
            }
        }

        // sigmoid in regs, keep tf32 bit pattern in the same registers
#pragma unroll
        for (int nt = 0; nt < 8; nt++)
#pragma unroll
            for (int l = 0; l < 4; l++) {
                float xv = fmaf(sacc[nt][l], scale, sbias);
                float sg = 1.f / (1.f + __expf(-xv));
                sacc[nt][l] = __uint_as_float(f2tf32(sg));
            }

        // ---- O-phase: O[16q x 64d] += S @ V; A-frag via shuffle transpose ----
#pragma unroll
        for (int s = 0; s < 8; s++) {
            // C-frag (r,2c),(r,2c+1),(r+8,2c),(r+8,2c+1)  ->  A-frag (r,c),(r+8,c),(r,c+4),(r+8,c+4)
            float x0 = __shfl_sync(0xffffffffu, sacc[s][0], srcA);
            float x1 = __shfl_sync(0xffffffffu, sacc[s][1], srcA);
            float y0 = __shfl_sync(0xffffffffu, sacc[s][2], srcA);
            float y1 = __shfl_sync(0xffffffffu, sacc[s][3], srcA);
            float z0 = __shfl_sync(0xffffffffu, sacc[s][0], srcB);
            float z1 = __shfl_sync(0xffffffffu, sacc[s][1], srcB);
            float w0 = __shfl_sync(0xffffffffu, sacc[s][2], srcB);
            float w1 = __shfl_sync(0xffffffffu, sacc[s][3], srcB);
            unsigned af[4];
            af[0] = __float_as_uint(odd ? x1 : x0);
            af[1] = __float_as_uint(odd ? y1 : y0);
            af[2] = __float_as_uint(odd ? z1 : z0);
            af[3] = __float_as_uint(odd ? w1 : w0);
#pragma unroll
            for (int nt = 0; nt < 8; nt++) {
                unsigned bf[2];
                bf[0] = Vs[(nt * 8 + r) * ATS + s * 8 + c];
                bf[1] = Vs[(nt * 8 + r) * ATS + s * 8 + c + 4];
                MMA_TF32(oacc[nt], af, bf);
            }
        }
    }

    // write O tile
#pragma unroll
    for (int l2 = 0; l2 < 2; l2++) {
        const size_t row = baseRow + (size_t)qt * 128 + q0 + r + 8 * l2;
#pragma unroll
        for (int nt = 0; nt < 8; nt++) {
            const int col = colBase + nt * 8 + 2 * c;
            *(float2*)(O + row * D_MODEL + col) =
                make_float2(oacc[nt][2 * l2 + 0], oacc[nt][2 * l2 + 1]);
        }
    }
}

// ---------------- residual + layernorm over 512 cols ---------------------------
__global__ __launch_bounds__(128)
void ln_res_kernel(const float* __restrict__ a, const float* __restrict__ t,
                   const float* __restrict__ gamma, const float* __restrict__ beta,
                   float* __restrict__ out)
{
    const int row = blockIdx.x;
    const int tid = threadIdx.x;      // 128 threads * 4 = 512
    const float4 va = ((const float4*)(a + (size_t)row * D_MODEL))[tid];
    const float4 vt = ((const float4*)(t + (size_t)row * D_MODEL))[tid];
    float v0 = va.x + vt.x, v1 = va.y + vt.y, v2 = va.z + vt.z, v3 = va.w + vt.w;

    float s  = v0 + v1 + v2 + v3;
    float ss = v0 * v0 + v1 * v1 + v2 * v2 + v3 * v3;
#pragma unroll
    for (int o = 16; o; o >>= 1) {
        s  += __shfl_xor_sync(0xffffffffu, s,  o);
        ss += __shfl_xor_sync(0xffffffffu, ss, o);
    }
    __shared__ float sh[8];
    if ((tid & 31) == 0) { sh[tid >> 5] = s; sh[4 + (tid >> 5)] = ss; }
    __syncthreads();
    float S2  = sh[0] + sh[1] + sh[2] + sh[3];
    float SS2 = sh[4] + sh[5] + sh[6] + sh[7];

    const float mu   = S2 * (1.f / 512.f);
    const float var  = SS2 * (1.f / 512.f) - mu * mu;
    const float rstd = rsqrtf(var + 1e-5f);

    const float4 g  = ((const float4*)gamma)[tid];
    const float4 bb = ((const float4*)beta)[tid];
    float4 o;
    o.x = (v0 - mu) * rstd * g.x + bb.x;
    o.y = (v1 - mu) * rstd * g.y + bb.y;
    o.z = (v2 - mu) * rstd * g.z + bb.z;
    o.w = (v3 - mu) * rstd * g.w + bb.w;
    ((float4*)(out + (size_t)row * D_MODEL))[tid] = o;
}

// ---------------- launch --------------------------------------------------------
extern "C" void kernel_launch(void* const* d_in, const int* in_sizes, int n_in,
                              void* d_out, int out_size)
{
    const float* x       = (const float*)d_in[0];
    const float* Wq      = (const float*)d_in[1];
    const float* Wk      = (const float*)d_in[2];
    const float* Wv      = (const float*)d_in[3];
    const float* dense_w = (const float*)d_in[4];
    const float* dense_b = (const float*)d_in[5];
    const float* ff1_w   = (const float*)d_in[6];
    const float* ff1_b   = (const float*)d_in[7];
    const float* ff2_w   = (const float*)d_in[8];
    const float* ff2_b   = (const float*)d_in[9];
    const float* ln1_g   = (const float*)d_in[10];
    const float* ln1_b   = (const float*)d_in[11];
    const float* ln2_g   = (const float*)d_in[12];
    const float* ln2_b   = (const float*)d_in[13];

    float *Q, *K, *V, *O, *T, *X1, *F;
    cudaGetSymbolAddress((void**)&Q,  g_Q);
    cudaGetSymbolAddress((void**)&K,  g_K);
    cudaGetSymbolAddress((void**)&V,  g_V);
    cudaGetSymbolAddress((void**)&O,  g_O);
    cudaGetSymbolAddress((void**)&T,  g_T);
    cudaGetSymbolAddress((void**)&X1, g_X1);
    cudaGetSymbolAddress((void**)&F,  g_F);

    dim3 blk(256);

    // Q,K,V projections (one launch, z selects weight)
    tgemm_qkv<<<dim3(D_MODEL / 128, MROWS / 128, 3), blk>>>(x, Wq, Wk, Wv, Q, K, V);

    // fused sigmoid attention
    const size_t asmem = (size_t)(128 * ATS + 64 * ATS + 64 * ATS) * sizeof(unsigned);
    cudaFuncSetAttribute(attn_tc2,
                         cudaFuncAttributeMaxDynamicSharedMemorySize, (int)asmem);
    attn_tc2<<<dim3(SEQ / 128, BATCH * NHEAD), blk, asmem>>>(
        Q, K, V, O, 0.125f, -8.317766166719343f);  // 1/sqrt(64), -log(4096)

    // dense + residual LN1
    tgemm<<<dim3(D_MODEL / 128, MROWS / 128), blk>>>(O, dense_w, T, D_MODEL, D_MODEL, dense_b, 0);
    ln_res_kernel<<<MROWS, 128>>>(x, T, ln1_g, ln1_b, X1);

    // FFN + residual LN2
    tgemm<<<dim3(DFF / 128, MROWS / 128), blk>>>(X1, ff1_w, F, DFF, D_MODEL, ff1_b, 1);
    tgemm<<<dim3(D_MODEL / 128, MROWS / 128), blk>>>(F, ff2_w, T, D_MODEL, DFF, ff2_b, 0);
    ln_res_kernel<<<MROWS, 128>>>(X1, T, ln2_g, ln2_b, (float*)d_out);
}

// round 9
// speedup vs baseline: 3.5580x; 1.4316x over previous
#include <cuda_runtime.h>
#include <math.h>

#define D_MODEL 512
#define SEQ     4096
#define BATCH   2
#define NHEAD   8
#define DHEAD   64
#define DFF     2048
#define MROWS   (BATCH*SEQ)   // 8192

// ---------------- scratch (static device globals; no allocation) ----------------
__device__ float g_Q [MROWS*D_MODEL];
__device__ float g_K [MROWS*D_MODEL];
__device__ float g_V [MROWS*D_MODEL];
__device__ float g_O [MROWS*D_MODEL];
__device__ float g_T [MROWS*D_MODEL];
__device__ float g_X1[MROWS*D_MODEL];
__device__ float g_F [MROWS*DFF];

// ---------------- async copy helpers --------------------------------------------
__device__ __forceinline__ void cp16(const void* smem_ptr, const void* gmem_ptr) {
    unsigned s = (unsigned)__cvta_generic_to_shared(smem_ptr);
    asm volatile("cp.async.cg.shared.global [%0], [%1], 16;" :: "r"(s), "l"(gmem_ptr));
}
#define CP_COMMIT() asm volatile("cp.async.commit_group;" ::: "memory")
#define CP_WAIT1()  asm volatile("cp.async.wait_group 1;" ::: "memory")

// D += A@B, m16n8k8 tf32 (raw fp32 bits; HW truncates to tf32)
#define MMA_TF32(d, a, b) \
    asm volatile("mma.sync.aligned.m16n8k8.row.col.f32.tf32.tf32.f32 " \
                 "{%0,%1,%2,%3},{%4,%5,%6,%7},{%8,%9},{%0,%1,%2,%3};" \
                 : "+f"((d)[0]), "+f"((d)[1]), "+f"((d)[2]), "+f"((d)[3]) \
                 : "r"((a)[0]), "r"((a)[1]), "r"((a)[2]), "r"((a)[3]), \
                   "r"((b)[0]), "r"((b)[1]))

// ================= tf32 GEMM: C[M,N] = A[M,K]@B[K,N] (+bias)(relu) ==============
// 128x128 tile, BK=16, 256 thr = 8 warps (4m x 2n), warp tile 32x64.
// 3-stage cp.async pipeline. As[m][k] stride 20 (bank 20r+c: distinct).
// Bs[k][n] stride 136 (bank 8c+r+8nt: distinct). All rows 16B-aligned.
#define AST 20
#define BST 136
#define A_STG (128*AST)
#define B_STG (16*BST)

#define G_ISSUE(t,s) { \
    float* ad = As_ + (s)*A_STG + aRow*AST + aK0; \
    const float* ag = Ag + (t)*16; \
    cp16(ad, ag); cp16(ad+4, ag+4); \
    float* bd = Bs_ + (s)*B_STG + bK*BST + bN0; \
    const float* bg = Bg + (size_t)(t)*16*N; \
    cp16(bd, bg); cp16(bd+4, bg+4); \
    CP_COMMIT(); }

__device__ __forceinline__
void gemm_body(const float* __restrict__ A, const float* __restrict__ B,
               float* __restrict__ C, int N, int K,
               const float* __restrict__ bias, int relu,
               int bx, int by, float* sm)
{
    float* As_ = sm;
    float* Bs_ = sm + 3 * A_STG;

    const int tid  = threadIdx.x;
    const int warp = tid >> 5;
    const int lane = tid & 31;
    const int r    = lane >> 2;
    const int c    = lane & 3;
    const int wm   = (warp & 3) * 32;
    const int wn   = (warp >> 2) * 64;

    const int aRow = tid >> 1, aK0 = (tid & 1) * 8;
    const int bK   = tid >> 4, bN0 = (tid & 15) * 8;

    const float* Ag = A + (size_t)(by * 128 + aRow) * K + aK0;
    const float* Bg = B + (size_t)bK * N + bx * 128 + bN0;

    const int T = K >> 4;

    G_ISSUE(0, 0);
    G_ISSUE(1, 1);

    float acc[2][8][4];
#pragma unroll
    for (int mt = 0; mt < 2; mt++)
#pragma unroll
        for (int nt = 0; nt < 8; nt++)
#pragma unroll
            for (int l = 0; l < 4; l++) acc[mt][nt][l] = 0.f;

    for (int t = 0; t < T; t++) {
        const int s = t % 3;
        CP_WAIT1();
        __syncthreads();          // stage t landed; all warps done with stage (t-1)%3
        if (t + 2 < T) { const int s2 = (t + 2) % 3; G_ISSUE(t + 2, s2); }

        const float* As = As_ + s * A_STG;
        const float* Bs = Bs_ + s * B_STG;
#pragma unroll
        for (int ks = 0; ks < 16; ks += 8) {
            unsigned af[2][4];
#pragma unroll
            for (int mt = 0; mt < 2; mt++) {
                const int mb = wm + mt * 16;
                af[mt][0] = __float_as_uint(As[(mb + r) * AST     + ks + c]);
                af[mt][1] = __float_as_uint(As[(mb + r + 8) * AST + ks + c]);
                af[mt][2] = __float_as_uint(As[(mb + r) * AST     + ks + c + 4]);
                af[mt][3] = __float_as_uint(As[(mb + r + 8) * AST + ks + c + 4]);
            }
#pragma unroll
            for (int nt = 0; nt < 8; nt++) {
                unsigned bf[2];
                bf[0] = __float_as_uint(Bs[(ks + c) * BST     + wn + nt * 8 + r]);
                bf[1] = __float_as_uint(Bs[(ks + c + 4) * BST + wn + nt * 8 + r]);
#pragma unroll
                for (int mt = 0; mt < 2; mt++)
                    MMA_TF32(acc[mt][nt], af[mt], bf);
            }
        }
    }

    // epilogue
#pragma unroll
    for (int mt = 0; mt < 2; mt++) {
#pragma unroll
        for (int l2 = 0; l2 < 2; l2++) {
            const int row = by * 128 + wm + mt * 16 + r + 8 * l2;
#pragma unroll
            for (int nt = 0; nt < 8; nt++) {
                const int col = bx * 128 + wn + nt * 8 + 2 * c;
                float v0 = acc[mt][nt][2 * l2 + 0];
                float v1 = acc[mt][nt][2 * l2 + 1];
                if (bias) { v0 += bias[col]; v1 += bias[col + 1]; }
                if (relu) { v0 = fmaxf(v0, 0.f); v1 = fmaxf(v1, 0.f); }
                *(float2*)(C + (size_t)row * N + col) = make_float2(v0, v1);
            }
        }
    }
}

extern __shared__ float dynsm[];

__global__ __launch_bounds__(256, 2)
void tgemm(const float* __restrict__ A, const float* __restrict__ B,
           float* __restrict__ C, int N, int K,
           const float* __restrict__ bias, int relu)
{
    gemm_body(A, B, C, N, K, bias, relu, blockIdx.x, blockIdx.y, dynsm);
}

__global__ __launch_bounds__(256, 2)
void tgemm_qkv(const float* __restrict__ A,
               const float* __restrict__ Wq, const float* __restrict__ Wk,
               const float* __restrict__ Wv,
               float* __restrict__ Q, float* __restrict__ K,
               float* __restrict__ V)
{
    const float* B = (blockIdx.z == 0) ? Wq : (blockIdx.z == 1) ? Wk : Wv;
    float*       C = (blockIdx.z == 0) ? Q  : (blockIdx.z == 1) ? K  : V;
    gemm_body(A, B, C, D_MODEL, D_MODEL, nullptr, 0, blockIdx.x, blockIdx.y, dynsm);
}

// ================= fused sigmoid-attention, cp.async double-buffered ============
// O[q,:] = sum_k sigmoid(q.k*scale + sbias) * V[k,:]
// CTA: 256 thr (8 warps), q-tile 128 (16 q/warp), k-tile 64, 2 CTAs/SM.
// smem: Qs[q][d] 128x68 + 2x { Ks[kk][d] 64x68, Vs[kk][d] 64x72 } = 104KB.
// S kept in registers; sigmoid = t - t^2 with t = expf(x) (x <= ~-7 always).
#define QST 68
#define KST 68
#define VST 72
#define K_STG (64*KST)
#define V_STG (64*VST)

#define A_ISSUE_KV(kt,s) { \
    const size_t grow = (baseRow + (size_t)(kt) * 64 + kr) * D_MODEL + colBase + kd0; \
    const float* kg = Kp + grow; \
    float* kd = Ks_ + (s)*K_STG + kr*KST + kd0; \
    cp16(kd, kg); cp16(kd+4, kg+4); cp16(kd+8, kg+8); cp16(kd+12, kg+12); \
    const float* vg = Vp + grow; \
    float* vd = Vs_ + (s)*V_STG + kr*VST + kd0; \
    cp16(vd, vg); cp16(vd+4, vg+4); cp16(vd+8, vg+8); cp16(vd+12, vg+12); \
    CP_COMMIT(); }

__global__ __launch_bounds__(256, 2)
void attn_tc3(const float* __restrict__ Qp, const float* __restrict__ Kp,
              const float* __restrict__ Vp, float* __restrict__ O,
              float scale, float sbias)
{
    float* Qs  = dynsm;                    // 128*68
    float* Ks_ = Qs + 128 * QST;           // 2 stages of 64*68
    float* Vs_ = Ks_ + 2 * K_STG;          // 2 stages of 64*72

    const int tid  = threadIdx.x;
    const int warp = tid >> 5;
    const int lane = tid & 31;
    const int r    = lane >> 2;
    const int c    = lane & 3;
    const int q0   = warp * 16;

    const int qt = blockIdx.x;             // 0..31
    const int bh = blockIdx.y;             // 0..15
    const int b  = bh >> 3, h = bh & 7;
    const size_t baseRow = (size_t)b * SEQ;
    const int colBase = h * DHEAD;

    const int kr = tid >> 2, kd0 = (tid & 3) * 16;

    // prologue group 0: Q tile + KV tile 0
    {
        const int qr = tid >> 1, qd0 = (tid & 1) * 32;
        const float* qg = Qp + (baseRow + (size_t)qt * 128 + qr) * D_MODEL + colBase + qd0;
        float* qd = Qs + qr * QST + qd0;
#pragma unroll
        for (int i = 0; i < 8; i++) cp16(qd + 4 * i, qg + 4 * i);

        const size_t grow = (baseRow + (size_t)kr) * D_MODEL + colBase + kd0;
        const float* kg = Kp + grow;
        float* kd = Ks_ + kr * KST + kd0;
        cp16(kd, kg); cp16(kd + 4, kg + 4); cp16(kd + 8, kg + 8); cp16(kd + 12, kg + 12);
        const float* vg = Vp + grow;
        float* vd = Vs_ + kr * VST + kd0;
        cp16(vd, vg); cp16(vd + 4, vg + 4); cp16(vd + 8, vg + 8); cp16(vd + 12, vg + 12);
        CP_COMMIT();
    }
    // group 1: KV tile 1
    A_ISSUE_KV(1, 1);

    float oacc[8][4];
#pragma unroll
    for (int nt = 0; nt < 8; nt++)
#pragma unroll
        for (int l = 0; l < 4; l++) oacc[nt][l] = 0.f;

    const int srcA = (lane & ~3) | (c >> 1);
    const int srcB = srcA | 2;
    const bool odd = (c & 1);

    for (int kt = 0; kt < SEQ / 64; kt++) {
        const int s = kt & 1;
        CP_WAIT1();
        __syncthreads();              // stage kt landed

        const float* Ks = Ks_ + s * K_STG;
        const float* Vs = Vs_ + s * V_STG;

        // ---- S-phase: S[16q x 64k] = Q @ K^T ----
        float sacc[8][4];
#pragma unroll
        for (int nt = 0; nt < 8; nt++)
#pragma unroll
            for (int l = 0; l < 4; l++) sacc[nt][l] = 0.f;

#pragma unroll
        for (int ks = 0; ks < 64; ks += 8) {
            unsigned af[4];
            af[0] = __float_as_uint(Qs[(q0 + r) * QST     + ks + c]);
            af[1] = __float_as_uint(Qs[(q0 + r + 8) * QST + ks + c]);
            af[2] = __float_as_uint(Qs[(q0 + r) * QST     + ks + c + 4]);
            af[3] = __float_as_uint(Qs[(q0 + r + 8) * QST + ks + c + 4]);
#pragma unroll
            for (int nt = 0; nt < 8; nt++) {
                unsigned bf[2];
                bf[0] = __float_as_uint(Ks[(nt * 8 + r) * KST + ks + c]);
                bf[1] = __float_as_uint(Ks[(nt * 8 + r) * KST + ks + c + 4]);
                MMA_TF32(sacc[nt], af, bf);
            }
        }

        // sigmoid(x) = t - t^2, t = exp(x); valid since x <= ~-7 here
#pragma unroll
        for (int nt = 0; nt < 8; nt++)
#pragma unroll
            for (int l = 0; l < 4; l++) {
                float xv = fmaf(sacc[nt][l], scale, sbias);
                float t  = __expf(xv);
                sacc[nt][l] = fmaf(-t, t, t);
            }

        // ---- O-phase: O[16q x 64d] += S @ V; A-frag via shuffle transpose ----
#pragma unroll
        for (int sc = 0; sc < 8; sc++) {
            float x0 = __shfl_sync(0xffffffffu, sacc[sc][0], srcA);
            float x1 = __shfl_sync(0xffffffffu, sacc[sc][1], srcA);
            float y0 = __shfl_sync(0xffffffffu, sacc[sc][2], srcA);
            float y1 = __shfl_sync(0xffffffffu, sacc[sc][3], srcA);
            float z0 = __shfl_sync(0xffffffffu, sacc[sc][0], srcB);
            float z1 = __shfl_sync(0xffffffffu, sacc[sc][1], srcB);
            float w0 = __shfl_sync(0xffffffffu, sacc[sc][2], srcB);
            float w1 = __shfl_sync(0xffffffffu, sacc[sc][3], srcB);
            unsigned af[4];
            af[0] = __float_as_uint(odd ? x1 : x0);
            af[1] = __float_as_uint(odd ? y1 : y0);
            af[2] = __float_as_uint(odd ? z1 : z0);
            af[3] = __float_as_uint(odd ? w1 : w0);
#pragma unroll
            for (int nt = 0; nt < 8; nt++) {
                unsigned bf[2];
                bf[0] = __float_as_uint(Vs[(sc * 8 + c) * VST     + nt * 8 + r]);
                bf[1] = __float_as_uint(Vs[(sc * 8 + c + 4) * VST + nt * 8 + r]);
                MMA_TF32(oacc[nt], af, bf);
            }
        }

        __syncthreads();              // all warps done with stage s
        if (kt + 2 < SEQ / 64) A_ISSUE_KV(kt + 2, s);
    }

    // write O tile
#pragma unroll
    for (int l2 = 0; l2 < 2; l2++) {
        const size_t row = baseRow + (size_t)qt * 128 + q0 + r + 8 * l2;
#pragma unroll
        for (int nt = 0; nt < 8; nt++) {
            const int col = colBase + nt * 8 + 2 * c;
            *(float2*)(O + row * D_MODEL + col) =
                make_float2(oacc[nt][2 * l2 + 0], oacc[nt][2 * l2 + 1]);
        }
    }
}

// ---------------- residual + layernorm over 512 cols ---------------------------
__global__ __launch_bounds__(128)
void ln_res_kernel(const float* __restrict__ a, const float* __restrict__ t,
                   const float* __restrict__ gamma, const float* __restrict__ beta,
                   float* __restrict__ out)
{
    const int row = blockIdx.x;
    const int tid = threadIdx.x;      // 128 threads * 4 = 512
    const float4 va = ((const float4*)(a + (size_t)row * D_MODEL))[tid];
    const float4 vt = ((const float4*)(t + (size_t)row * D_MODEL))[tid];
    float v0 = va.x + vt.x, v1 = va.y + vt.y, v2 = va.z + vt.z, v3 = va.w + vt.w;

    float s  = v0 + v1 + v2 + v3;
    float ss = v0 * v0 + v1 * v1 + v2 * v2 + v3 * v3;
#pragma unroll
    for (int o = 16; o; o >>= 1) {
        s  += __shfl_xor_sync(0xffffffffu, s,  o);
        ss += __shfl_xor_sync(0xffffffffu, ss, o);
    }
    __shared__ float sh[8];
    if ((tid & 31) == 0) { sh[tid >> 5] = s; sh[4 + (tid >> 5)] = ss; }
    __syncthreads();
    float S2  = sh[0] + sh[1] + sh[2] + sh[3];
    float SS2 = sh[4] + sh[5] + sh[6] + sh[7];

    const float mu   = S2 * (1.f / 512.f);
    const float var  = SS2 * (1.f / 512.f) - mu * mu;
    const float rstd = rsqrtf(var + 1e-5f);

    const float4 g  = ((const float4*)gamma)[tid];
    const float4 bb = ((const float4*)beta)[tid];
    float4 o;
    o.x = (v0 - mu) * rstd * g.x + bb.x;
    o.y = (v1 - mu) * rstd * g.y + bb.y;
    o.z = (v2 - mu) * rstd * g.z + bb.z;
    o.w = (v3 - mu) * rstd * g.w + bb.w;
    ((float4*)(out + (size_t)row * D_MODEL))[tid] = o;
}

// ---------------- launch --------------------------------------------------------
extern "C" void kernel_launch(void* const* d_in, const int* in_sizes, int n_in,
                              void* d_out, int out_size)
{
    const float* x       = (const float*)d_in[0];
    const float* Wq      = (const float*)d_in[1];
    const float* Wk      = (const float*)d_in[2];
    const float* Wv      = (const float*)d_in[3];
    const float* dense_w = (const float*)d_in[4];
    const float* dense_b = (const float*)d_in[5];
    const float* ff1_w   = (const float*)d_in[6];
    const float* ff1_b   = (const float*)d_in[7];
    const float* ff2_w   = (const float*)d_in[8];
    const float* ff2_b   = (const float*)d_in[9];
    const float* ln1_g   = (const float*)d_in[10];
    const float* ln1_b   = (const float*)d_in[11];
    const float* ln2_g   = (const float*)d_in[12];
    const float* ln2_b   = (const float*)d_in[13];

    float *Q, *K, *V, *O, *T, *X1, *F;
    cudaGetSymbolAddress((void**)&Q,  g_Q);
    cudaGetSymbolAddress((void**)&K,  g_K);
    cudaGetSymbolAddress((void**)&V,  g_V);
    cudaGetSymbolAddress((void**)&O,  g_O);
    cudaGetSymbolAddress((void**)&T,  g_T);
    cudaGetSymbolAddress((void**)&X1, g_X1);
    cudaGetSymbolAddress((void**)&F,  g_F);

    const int gemm_smem = (3 * A_STG + 3 * B_STG) * 4;                 // 56832 B
    const int attn_smem = (128 * QST + 2 * K_STG + 2 * V_STG) * 4;     // 106496 B
    cudaFuncSetAttribute(tgemm,     cudaFuncAttributeMaxDynamicSharedMemorySize, gemm_smem);
    cudaFuncSetAttribute(tgemm_qkv, cudaFuncAttributeMaxDynamicSharedMemorySize, gemm_smem);
    cudaFuncSetAttribute(attn_tc3,  cudaFuncAttributeMaxDynamicSharedMemorySize, attn_smem);

    dim3 blk(256);

    // Q,K,V projections (one launch, z selects weight)
    tgemm_qkv<<<dim3(D_MODEL / 128, MROWS / 128, 3), blk, gemm_smem>>>(x, Wq, Wk, Wv, Q, K, V);

    // fused sigmoid attention
    attn_tc3<<<dim3(SEQ / 128, BATCH * NHEAD), blk, attn_smem>>>(
        Q, K, V, O, 0.125f, -8.317766166719343f);  // 1/sqrt(64), -log(4096)

    // dense + residual LN1
    tgemm<<<dim3(D_MODEL / 128, MROWS / 128), blk, gemm_smem>>>(O, dense_w, T, D_MODEL, D_MODEL, dense_b, 0);
    ln_res_kernel<<<MROWS, 128>>>(x, T, ln1_g, ln1_b, X1);

    // FFN + residual LN2
    tgemm<<<dim3(DFF / 128, MROWS / 128), blk, gemm_smem>>>(X1, ff1_w, F, DFF, D_MODEL, ff1_b, 1);
    tgemm<<<dim3(D_MODEL / 128, MROWS / 128), blk, gemm_smem>>>(F, ff2_w, T, D_MODEL, DFF, ff2_b, 0);
    ln_res_kernel<<<MROWS, 128>>>(X1, T, ln2_g, ln2_b, (float*)d_out);
}

// round 10
// speedup vs baseline: 5.2993x; 1.4894x over previous
#include <cuda_runtime.h>
#include <math.h>

#define D_MODEL 512
#define SEQ     4096
#define BATCH   2
#define NHEAD   8
#define DHEAD   64
#define DFF     2048
#define MROWS   (BATCH*SEQ)   // 8192

typedef unsigned short u16;

// ---------------- scratch (static device globals; no allocation) ----------------
__device__ u16   g_Qh[MROWS*D_MODEL];          // bf16 Q
__device__ u16   g_Kh[MROWS*D_MODEL];          // bf16 K
__device__ u16   g_Vh[MROWS*D_MODEL];          // bf16 V (natural layout)
__device__ u16   g_Vt[BATCH*NHEAD*DHEAD*SEQ];  // bf16 V transposed [bh][d][s]
__device__ float g_O [MROWS*D_MODEL];
__device__ float g_T [MROWS*D_MODEL];
__device__ float g_X1[MROWS*D_MODEL];
__device__ float g_F [MROWS*DFF];

// ---------------- async copy helpers --------------------------------------------
__device__ __forceinline__ void cp16(const void* smem_ptr, const void* gmem_ptr) {
    unsigned s = (unsigned)__cvta_generic_to_shared(smem_ptr);
    asm volatile("cp.async.cg.shared.global [%0], [%1], 16;" :: "r"(s), "l"(gmem_ptr));
}
#define CP_COMMIT() asm volatile("cp.async.commit_group;" ::: "memory")
#define CP_WAIT1()  asm volatile("cp.async.wait_group 1;" ::: "memory")

// D += A@B, m16n8k8 tf32 (raw fp32 bits; HW truncates to tf32)
#define MMA_TF32(d, a, b) \
    asm volatile("mma.sync.aligned.m16n8k8.row.col.f32.tf32.tf32.f32 " \
                 "{%0,%1,%2,%3},{%4,%5,%6,%7},{%8,%9},{%0,%1,%2,%3};" \
                 : "+f"((d)[0]), "+f"((d)[1]), "+f"((d)[2]), "+f"((d)[3]) \
                 : "r"((a)[0]), "r"((a)[1]), "r"((a)[2]), "r"((a)[3]), \
                   "r"((b)[0]), "r"((b)[1]))

// D += A@B, m16n8k16 bf16
#define MMA_BF16(d, a0, a1, a2, a3, b0, b1) \
    asm volatile("mma.sync.aligned.m16n8k16.row.col.f32.bf16.bf16.f32 " \
                 "{%0,%1,%2,%3},{%4,%5,%6,%7},{%8,%9},{%0,%1,%2,%3};" \
                 : "+f"((d)[0]), "+f"((d)[1]), "+f"((d)[2]), "+f"((d)[3]) \
                 : "r"(a0), "r"(a1), "r"(a2), "r"(a3), "r"(b0), "r"(b1))

// pack two fp32 -> bf16x2 {lo, hi}
__device__ __forceinline__ unsigned pack_bf16(float lo, float hi) {
    unsigned d;
    asm("cvt.rn.bf16x2.f32 %0, %1, %2;" : "=r"(d) : "f"(hi), "f"(lo));
    return d;
}

// ================= tf32 GEMM: C[M,N] = A[M,K]@B[K,N] (+bias)(relu) ==============
// 128x128 tile, BK=16, 256 thr = 8 warps (4m x 2n), warp tile 32x64.
// 3-stage cp.async pipeline. Optional bf16 output (C16 != nullptr).
#define AST 20
#define BST 136
#define A_STG (128*AST)
#define B_STG (16*BST)

#define G_ISSUE(t,s) { \
    float* ad = As_ + (s)*A_STG + aRow*AST + aK0; \
    const float* ag = Ag + (t)*16; \
    cp16(ad, ag); cp16(ad+4, ag+4); \
    float* bd = Bs_ + (s)*B_STG + bK*BST + bN0; \
    const float* bg = Bg + (size_t)(t)*16*N; \
    cp16(bd, bg); cp16(bd+4, bg+4); \
    CP_COMMIT(); }

__device__ __forceinline__
void gemm_body(const float* __restrict__ A, const float* __restrict__ B,
               float* __restrict__ C, u16* __restrict__ C16, int N, int K,
               const float* __restrict__ bias, int relu,
               int bx, int by, float* sm)
{
    float* As_ = sm;
    float* Bs_ = sm + 3 * A_STG;

    const int tid  = threadIdx.x;
    const int warp = tid >> 5;
    const int lane = tid & 31;
    const int r    = lane >> 2;
    const int c    = lane & 3;
    const int wm   = (warp & 3) * 32;
    const int wn   = (warp >> 2) * 64;

    const int aRow = tid >> 1, aK0 = (tid & 1) * 8;
    const int bK   = tid >> 4, bN0 = (tid & 15) * 8;

    const float* Ag = A + (size_t)(by * 128 + aRow) * K + aK0;
    const float* Bg = B + (size_t)bK * N + bx * 128 + bN0;

    const int T = K >> 4;

    G_ISSUE(0, 0);
    G_ISSUE(1, 1);

    float acc[2][8][4];
#pragma unroll
    for (int mt = 0; mt < 2; mt++)
#pragma unroll
        for (int nt = 0; nt < 8; nt++)
#pragma unroll
            for (int l = 0; l < 4; l++) acc[mt][nt][l] = 0.f;

    for (int t = 0; t < T; t++) {
        const int s = t % 3;
        CP_WAIT1();
        __syncthreads();          // stage t landed; all warps done with stage (t-1)%3
        if (t + 2 < T) { const int s2 = (t + 2) % 3; G_ISSUE(t + 2, s2); }

        const float* As = As_ + s * A_STG;
        const float* Bs = Bs_ + s * B_STG;
#pragma unroll
        for (int ks = 0; ks < 16; ks += 8) {
            unsigned af[2][4];
#pragma unroll
            for (int mt = 0; mt < 2; mt++) {
                const int mb = wm + mt * 16;
                af[mt][0] = __float_as_uint(As[(mb + r) * AST     + ks + c]);
                af[mt][1] = __float_as_uint(As[(mb + r + 8) * AST + ks + c]);
                af[mt][2] = __float_as_uint(As[(mb + r) * AST     + ks + c + 4]);
                af[mt][3] = __float_as_uint(As[(mb + r + 8) * AST + ks + c + 4]);
            }
#pragma unroll
            for (int nt = 0; nt < 8; nt++) {
                unsigned bf[2];
                bf[0] = __float_as_uint(Bs[(ks + c) * BST     + wn + nt * 8 + r]);
                bf[1] = __float_as_uint(Bs[(ks + c + 4) * BST + wn + nt * 8 + r]);
#pragma unroll
                for (int mt = 0; mt < 2; mt++)
                    MMA_TF32(acc[mt][nt], af[mt], bf);
            }
        }
    }

    // epilogue
#pragma unroll
    for (int mt = 0; mt < 2; mt++) {
#pragma unroll
        for (int l2 = 0; l2 < 2; l2++) {
            const int row = by * 128 + wm + mt * 16 + r + 8 * l2;
#pragma unroll
            for (int nt = 0; nt < 8; nt++) {
                const int col = bx * 128 + wn + nt * 8 + 2 * c;
                float v0 = acc[mt][nt][2 * l2 + 0];
                float v1 = acc[mt][nt][2 * l2 + 1];
                if (bias) { v0 += bias[col]; v1 += bias[col + 1]; }
                if (relu) { v0 = fmaxf(v0, 0.f); v1 = fmaxf(v1, 0.f); }
                if (C16) {
                    *(unsigned*)&C16[(size_t)row * N + col] = pack_bf16(v0, v1);
                } else {
                    *(float2*)(C + (size_t)row * N + col) = make_float2(v0, v1);
                }
            }
        }
    }
}

extern __shared__ float dynsm[];

__global__ __launch_bounds__(256, 2)
void tgemm(const float* __restrict__ A, const float* __restrict__ B,
           float* __restrict__ C, int N, int K,
           const float* __restrict__ bias, int relu)
{
    gemm_body(A, B, C, nullptr, N, K, bias, relu, blockIdx.x, blockIdx.y, dynsm);
}

__global__ __launch_bounds__(256, 2)
void tgemm_qkv(const float* __restrict__ A,
               const float* __restrict__ Wq, const float* __restrict__ Wk,
               const float* __restrict__ Wv,
               u16* __restrict__ Q, u16* __restrict__ K, u16* __restrict__ V)
{
    const float* B = (blockIdx.z == 0) ? Wq : (blockIdx.z == 1) ? Wk : Wv;
    u16*         C = (blockIdx.z == 0) ? Q  : (blockIdx.z == 1) ? K  : V;
    gemm_body(A, B, nullptr, C, D_MODEL, D_MODEL, nullptr, 0, blockIdx.x, blockIdx.y, dynsm);
}

// ================= V transpose: g_Vh [b,s][h,d] bf16 -> g_Vt [bh][d][s] =========
__global__ __launch_bounds__(256)
void vtrans(const u16* __restrict__ Vh, u16* __restrict__ Vt)
{
    __shared__ u16 t[64][72];
    const int tid = threadIdx.x;
    const int bh = blockIdx.y, b = bh >> 3, h = bh & 7;
    const int s0 = blockIdx.x * 64;

    const int sr = tid >> 2, sc0 = (tid & 3) * 16;
    const u16* src = Vh + (size_t)(b * SEQ + s0 + sr) * D_MODEL + h * DHEAD + sc0;
    *(uint4*)&t[sr][sc0]     = *(const uint4*)(src);
    *(uint4*)&t[sr][sc0 + 8] = *(const uint4*)(src + 8);
    __syncthreads();

    const int dd = tid >> 2, j0 = (tid & 3) * 2;
    u16* dst = Vt + ((size_t)bh * DHEAD + dd) * SEQ + s0;
#pragma unroll
    for (int jj = 0; jj < 2; jj++) {
        u16 buf[8];
#pragma unroll
        for (int i = 0; i < 8; i++) buf[i] = t[(j0 + jj) * 8 + i][dd];
        *(uint4*)(dst + (j0 + jj) * 8) = *(uint4*)buf;
    }
}

// ================= fused sigmoid-attention, bf16 m16n8k16 =======================
// O[q,:] = sum_k sigmoid(q.k*scale + sbias) * V[k,:]
// CTA: 256 thr (8 warps), q-tile 128 (16 q/warp), k-tile 64, 2 CTAs/SM.
// smem (bf16): Qs[q][d] 128x72 + 2x { Ks[kk][d] 64x72, Vs[d][kk] 64x72 } = 54KB.
// S stays in C-frag registers; bf16x2 A-frag for O-phase = packed C-frag pairs
// (no shuffle). Strides 72 u16 = 36 words (== 4 mod 32): conflict-free 32b loads.
#define HS  72
#define KSTG (64*HS)

#define A_ISSUE_KV(kt,s) { \
    const u16* kg = Kp + (baseRow + (size_t)(kt) * 64 + kr) * D_MODEL + colBase + kd0; \
    u16* kd = Ks_ + (s)*KSTG + kr*HS + kd0; \
    cp16(kd, kg); cp16(kd + 8, kg + 8); \
    const u16* vg = Vtp + ((size_t)bh * DHEAD + kr) * SEQ + (size_t)(kt) * 64 + kd0; \
    u16* vd = Vs_ + (s)*KSTG + kr*HS + kd0; \
    cp16(vd, vg); cp16(vd + 8, vg + 8); \
    CP_COMMIT(); }

__global__ __launch_bounds__(256, 2)
void attn_bf16(const u16* __restrict__ Qp, const u16* __restrict__ Kp,
               const u16* __restrict__ Vtp, float* __restrict__ O,
               float scale, float sbias)
{
    u16* Qs  = (u16*)dynsm;                // 128*72
    u16* Ks_ = Qs + 128 * HS;              // 2 stages of 64*72
    u16* Vs_ = Ks_ + 2 * KSTG;             // 2 stages of 64*72

    const int tid  = threadIdx.x;
    const int warp = tid >> 5;
    const int lane = tid & 31;
    const int r    = lane >> 2;
    const int c    = lane & 3;
    const int q0   = warp * 16;

    const int qt = blockIdx.x;             // 0..31
    const int bh = blockIdx.y;             // 0..15
    const int b  = bh >> 3, h = bh & 7;
    const size_t baseRow = (size_t)b * SEQ;
    const int colBase = h * DHEAD;

    const int kr = tid >> 2, kd0 = (tid & 3) * 16;

    // prologue group 0: Q tile + KV tile 0
    {
        const int qr = tid >> 1, qd0 = (tid & 1) * 32;
        const u16* qg = Qp + (baseRow + (size_t)qt * 128 + qr) * D_MODEL + colBase + qd0;
        u16* qd = Qs + qr * HS + qd0;
#pragma unroll
        for (int i = 0; i < 4; i++) cp16(qd + 8 * i, qg + 8 * i);

        const u16* kg = Kp + (baseRow + (size_t)kr) * D_MODEL + colBase + kd0;
        u16* kd = Ks_ + kr * HS + kd0;
        cp16(kd, kg); cp16(kd + 8, kg + 8);
        const u16* vg = Vtp + ((size_t)bh * DHEAD + kr) * SEQ + kd0;
        u16* vd = Vs_ + kr * HS + kd0;
        cp16(vd, vg); cp16(vd + 8, vg + 8);
        CP_COMMIT();
    }
    // group 1: KV tile 1
    A_ISSUE_KV(1, 1);

    float oacc[8][4];
#pragma unroll
    for (int nt = 0; nt < 8; nt++)
#pragma unroll
        for (int l = 0; l < 4; l++) oacc[nt][l] = 0.f;

    for (int kt = 0; kt < SEQ / 64; kt++) {
        const int s = kt & 1;
        CP_WAIT1();
        __syncthreads();              // stage kt landed

        const u16* Ks = Ks_ + s * KSTG;
        const u16* Vs = Vs_ + s * KSTG;

        // ---- S-phase: S[16q x 64kk] = Q @ K^T  (K = d = 64, 4 k16 chunks) ----
        float sacc[8][4];
#pragma unroll
        for (int nt = 0; nt < 8; nt++)
#pragma unroll
            for (int l = 0; l < 4; l++) sacc[nt][l] = 0.f;

#pragma unroll
        for (int j = 0; j < 4; j++) {
            const int d0 = j * 16 + 2 * c;
            unsigned a0 = *(const unsigned*)&Qs[(q0 + r) * HS     + d0];
            unsigned a1 = *(const unsigned*)&Qs[(q0 + r + 8) * HS + d0];
            unsigned a2 = *(const unsigned*)&Qs[(q0 + r) * HS     + d0 + 8];
            unsigned a3 = *(const unsigned*)&Qs[(q0 + r + 8) * HS + d0 + 8];
#pragma unroll
            for (int nt = 0; nt < 8; nt++) {
                unsigned b0 = *(const unsigned*)&Ks[(nt * 8 + r) * HS + d0];
                unsigned b1 = *(const unsigned*)&Ks[(nt * 8 + r) * HS + d0 + 8];
                MMA_BF16(sacc[nt], a0, a1, a2, a3, b0, b1);
            }
        }

        // sigmoid(x) = t - t^2, t = exp(x); valid since x <= ~-7 here
#pragma unroll
        for (int nt = 0; nt < 8; nt++)
#pragma unroll
            for (int l = 0; l < 4; l++) {
                float xv = fmaf(sacc[nt][l], scale, sbias);
                float t  = __expf(xv);
                sacc[nt][l] = fmaf(-t, t, t);
            }

        // ---- O-phase: O[16q x 64d] += S @ V  (K = kk = 64, 4 k16 chunks) ----
        // A-frag = packed C-frag pairs (layouts coincide); B from Vt[d][kk].
#pragma unroll
        for (int j = 0; j < 4; j++) {
            unsigned a0 = pack_bf16(sacc[2 * j][0],     sacc[2 * j][1]);
            unsigned a1 = pack_bf16(sacc[2 * j][2],     sacc[2 * j][3]);
            unsigned a2 = pack_bf16(sacc[2 * j + 1][0], sacc[2 * j + 1][1]);
            unsigned a3 = pack_bf16(sacc[2 * j + 1][2], sacc[2 * j + 1][3]);
            const int k0 = j * 16 + 2 * c;
#pragma unroll
            for (int nt = 0; nt < 8; nt++) {
                unsigned b0 = *(const unsigned*)&Vs[(nt * 8 + r) * HS + k0];
                unsigned b1 = *(const unsigned*)&Vs[(nt * 8 + r) * HS + k0 + 8];
                MMA_BF16(oacc[nt], a0, a1, a2, a3, b0, b1);
            }
        }

        __syncthreads();              // all warps done with stage s
        if (kt + 2 < SEQ / 64) A_ISSUE_KV(kt + 2, s);
    }

    // write O tile (fp32)
#pragma unroll
    for (int l2 = 0; l2 < 2; l2++) {
        const size_t row = baseRow + (size_t)qt * 128 + q0 + r + 8 * l2;
#pragma unroll
        for (int nt = 0; nt < 8; nt++) {
            const int col = colBase + nt * 8 + 2 * c;
            *(float2*)(O + row * D_MODEL + col) =
                make_float2(oacc[nt][2 * l2 + 0], oacc[nt][2 * l2 + 1]);
        }
    }
}

// ---------------- residual + layernorm over 512 cols ---------------------------
__global__ __launch_bounds__(128)
void ln_res_kernel(const float* __restrict__ a, const float* __restrict__ t,
                   const float* __restrict__ gamma, const float* __restrict__ beta,
                   float* __restrict__ out)
{
    const int row = blockIdx.x;
    const int tid = threadIdx.x;      // 128 threads * 4 = 512
    const float4 va = ((const float4*)(a + (size_t)row * D_MODEL))[tid];
    const float4 vt = ((const float4*)(t + (size_t)row * D_MODEL))[tid];
    float v0 = va.x + vt.x, v1 = va.y + vt.y, v2 = va.z + vt.z, v3 = va.w + vt.w;

    float s  = v0 + v1 + v2 + v3;
    float ss = v0 * v0 + v1 * v1 + v2 * v2 + v3 * v3;
#pragma unroll
    for (int o = 16; o; o >>= 1) {
        s  += __shfl_xor_sync(0xffffffffu, s,  o);
        ss += __shfl_xor_sync(0xffffffffu, ss, o);
    }
    __shared__ float sh[8];
    if ((tid & 31) == 0) { sh[tid >> 5] = s; sh[4 + (tid >> 5)] = ss; }
    __syncthreads();
    float S2  = sh[0] + sh[1] + sh[2] + sh[3];
    float SS2 = sh[4] + sh[5] + sh[6] + sh[7];

    const float mu   = S2 * (1.f / 512.f);
    const float var  = SS2 * (1.f / 512.f) - mu * mu;
    const float rstd = rsqrtf(var + 1e-5f);

    const float4 g  = ((const float4*)gamma)[tid];
    const float4 bb = ((const float4*)beta)[tid];
    float4 o;
    o.x = (v0 - mu) * rstd * g.x + bb.x;
    o.y = (v1 - mu) * rstd * g.y + bb.y;
    o.z = (v2 - mu) * rstd * g.z + bb.z;
    o.w = (v3 - mu) * rstd * g.w + bb.w;
    ((float4*)(out + (size_t)row * D_MODEL))[tid] = o;
}

// ---------------- launch --------------------------------------------------------
extern "C" void kernel_launch(void* const* d_in, const int* in_sizes, int n_in,
                              void* d_out, int out_size)
{
    const float* x       = (const float*)d_in[0];
    const float* Wq      = (const float*)d_in[1];
    const float* Wk      = (const float*)d_in[2];
    const float* Wv      = (const float*)d_in[3];
    const float* dense_w = (const float*)d_in[4];
    const float* dense_b = (const float*)d_in[5];
    const float* ff1_w   = (const float*)d_in[6];
    const float* ff1_b   = (const float*)d_in[7];
    const float* ff2_w   = (const float*)d_in[8];
    const float* ff2_b   = (const float*)d_in[9];
    const float* ln1_g   = (const float*)d_in[10];
    const float* ln1_b   = (const float*)d_in[11];
    const float* ln2_g   = (const float*)d_in[12];
    const float* ln2_b   = (const float*)d_in[13];

    u16 *Qh, *Kh, *Vh, *Vt;
    float *O, *T, *X1, *F;
    cudaGetSymbolAddress((void**)&Qh, g_Qh);
    cudaGetSymbolAddress((void**)&Kh, g_Kh);
    cudaGetSymbolAddress((void**)&Vh, g_Vh);
    cudaGetSymbolAddress((void**)&Vt, g_Vt);
    cudaGetSymbolAddress((void**)&O,  g_O);
    cudaGetSymbolAddress((void**)&T,  g_T);
    cudaGetSymbolAddress((void**)&X1, g_X1);
    cudaGetSymbolAddress((void**)&F,  g_F);

    const int gemm_smem = (3 * A_STG + 3 * B_STG) * 4;        // 56832 B
    const int attn_smem = (128 * HS + 4 * KSTG) * 2;          // 55296 B
    cudaFuncSetAttribute(tgemm,     cudaFuncAttributeMaxDynamicSharedMemorySize, gemm_smem);
    cudaFuncSetAttribute(tgemm_qkv, cudaFuncAttributeMaxDynamicSharedMemorySize, gemm_smem);
    cudaFuncSetAttribute(attn_bf16, cudaFuncAttributeMaxDynamicSharedMemorySize, attn_smem);

    dim3 blk(256);

    // Q,K,V projections (tf32, bf16 outputs)
    tgemm_qkv<<<dim3(D_MODEL / 128, MROWS / 128, 3), blk, gemm_smem>>>(x, Wq, Wk, Wv, Qh, Kh, Vh);

    // V transpose to [bh][d][s]
    vtrans<<<dim3(SEQ / 64, BATCH * NHEAD), blk>>>(Vh, Vt);

    // fused sigmoid attention (bf16 tensor cores)
    attn_bf16<<<dim3(SEQ / 128, BATCH * NHEAD), blk, attn_smem>>>(
        Qh, Kh, Vt, O, 0.125f, -8.317766166719343f);  // 1/sqrt(64), -log(4096)

    // dense + residual LN1
    tgemm<<<dim3(D_MODEL / 128, MROWS / 128), blk, gemm_smem>>>(O, dense_w, T, D_MODEL, D_MODEL, dense_b, 0);
    ln_res_kernel<<<MROWS, 128>>>(x, T, ln1_g, ln1_b, X1);

    // FFN + residual LN2
    tgemm<<<dim3(DFF / 128, MROWS / 128), blk, gemm_smem>>>(X1, ff1_w, F, DFF, D_MODEL, ff1_b, 1);
    tgemm<<<dim3(D_MODEL / 128, MROWS / 128), blk, gemm_smem>>>(F, ff2_w, T, D_MODEL, DFF, ff2_b, 0);
    ln_res_kernel<<<MROWS, 128>>>(X1, T, ln2_g, ln2_b, (float*)d_out);
}

// round 12
// speedup vs baseline: 6.9773x; 1.3166x over previous
#include <cuda_runtime.h>
#include <cuda_fp16.h>
#include <math.h>

#define D_MODEL 512
#define SEQ     4096
#define BATCH   2
#define NHEAD   8
#define DHEAD   64
#define DFF     2048
#define MROWS   (BATCH*SEQ)   // 8192

typedef unsigned short u16;

// ---------------- scratch (static device globals; no allocation) ----------------
__device__ u16   g_x16[MROWS*D_MODEL];          // fp16 x
__device__ u16   g_Wqt[D_MODEL*D_MODEL];        // fp16 Wq^T [N][K]
__device__ u16   g_Wkt[D_MODEL*D_MODEL];
__device__ u16   g_Wvt[D_MODEL*D_MODEL];
__device__ u16   g_Wdt[D_MODEL*D_MODEL];        // dense_w^T
__device__ u16   g_W1t[DFF*D_MODEL];            // ff1_w^T [2048][512]
__device__ u16   g_W2t[D_MODEL*DFF];            // ff2_w^T [512][2048]
__device__ u16   g_Qh[MROWS*D_MODEL];           // fp16 Q
__device__ u16   g_Kh[MROWS*D_MODEL];           // fp16 K
__device__ u16   g_Vh[MROWS*D_MODEL];           // fp16 V (natural layout)
__device__ u16   g_Vt[BATCH*NHEAD*DHEAD*SEQ];   // fp16 V transposed [bh][d][s]
__device__ u16   g_O16[MROWS*D_MODEL];          // fp16 attention out
__device__ u16   g_X1h[MROWS*D_MODEL];          // fp16 x1
__device__ u16   g_F16[MROWS*DFF];              // fp16 relu(ff1)
__device__ float g_T [MROWS*D_MODEL];
__device__ float g_X1[MROWS*D_MODEL];

// ---------------- helpers --------------------------------------------------------
__device__ __forceinline__ void cp16(const void* smem_ptr, const void* gmem_ptr) {
    unsigned s = (unsigned)__cvta_generic_to_shared(smem_ptr);
    asm volatile("cp.async.cg.shared.global [%0], [%1], 16;" :: "r"(s), "l"(gmem_ptr));
}
#define CP_COMMIT() asm volatile("cp.async.commit_group;" ::: "memory")
#define CP_WAIT1()  asm volatile("cp.async.wait_group 1;" ::: "memory")

// D += A@B, m16n8k16 fp16, fp32 accum
#define MMA_F16(d, a0, a1, a2, a3, b0, b1) \
    asm volatile("mma.sync.aligned.m16n8k16.row.col.f32.f16.f16.f32 " \
                 "{%0,%1,%2,%3},{%4,%5,%6,%7},{%8,%9},{%0,%1,%2,%3};" \
                 : "+f"((d)[0]), "+f"((d)[1]), "+f"((d)[2]), "+f"((d)[3]) \
                 : "r"(a0), "r"(a1), "r"(a2), "r"(a3), "r"(b0), "r"(b1))

__device__ __forceinline__ unsigned pack_f16(float lo, float hi) {
    __half2 h = __floats2half2_rn(lo, hi);
    return *reinterpret_cast<unsigned*>(&h);
}

// ================= fp16 GEMM: C[M,N] = A[M,K]@Bt[N,K]^T (+bias)(relu) ===========
// 128x128 tile, BK=32, 256 thr = 8 warps (4m x 2n), warp tile 32x64.
// 3-stage cp.async. Both operands K-minor fp16, stride 40 halves = 20 words:
// fragment bank = (20r+c) mod 32, all 32 distinct -> conflict-free.
#define HST 40
#define HSTG (128*HST)

#define G16_ISSUE(t,s) { \
    u16* ad = As_ + (s)*HSTG + aRow*HST + aK0; \
    const u16* ag = Ag + (t)*32; \
    cp16(ad, ag); cp16(ad + 8, ag + 8); \
    u16* bd = Bs_ + (s)*HSTG + aRow*HST + aK0; \
    const u16* bg = Bg + (t)*32; \
    cp16(bd, bg); cp16(bd + 8, bg + 8); \
    CP_COMMIT(); }

__device__ __forceinline__
void gemm16_body(const u16* __restrict__ A, const u16* __restrict__ Bt,
                 float* __restrict__ C, u16* __restrict__ C16, int N, int K,
                 const float* __restrict__ bias, int relu,
                 int bx, int by, u16* sm)
{
    u16* As_ = sm;
    u16* Bs_ = sm + 3 * HSTG;

    const int tid  = threadIdx.x;
    const int warp = tid >> 5;
    const int lane = tid & 31;
    const int r    = lane >> 2;
    const int c    = lane & 3;
    const int wm   = (warp & 3) * 32;
    const int wn   = (warp >> 2) * 64;

    const int aRow = tid >> 1, aK0 = (tid & 1) * 16;   // same map for A rows / B rows

    const u16* Ag = A  + (size_t)(by * 128 + aRow) * K + aK0;
    const u16* Bg = Bt + (size_t)(bx * 128 + aRow) * K + aK0;

    const int T = K >> 5;

    G16_ISSUE(0, 0);
    G16_ISSUE(1, 1);

    float acc[2][8][4];
#pragma unroll
    for (int mt = 0; mt < 2; mt++)
#pragma unroll
        for (int nt = 0; nt < 8; nt++)
#pragma unroll
            for (int l = 0; l < 4; l++) acc[mt][nt][l] = 0.f;

    for (int t = 0; t < T; t++) {
        const int s = t % 3;
        CP_WAIT1();
        __syncthreads();          // stage t landed; all warps done with stage (t-1)%3
        if (t + 2 < T) { const int s2 = (t + 2) % 3; G16_ISSUE(t + 2, s2); }

        const u16* As = As_ + s * HSTG;
        const u16* Bs = Bs_ + s * HSTG;
#pragma unroll
        for (int j = 0; j < 2; j++) {           // two k16 chunks
            const int k0 = j * 16 + 2 * c;
            unsigned af[2][4];
#pragma unroll
            for (int mt = 0; mt < 2; mt++) {
                const int mb = wm + mt * 16;
                af[mt][0] = *(const unsigned*)&As[(mb + r) * HST     + k0];
                af[mt][1] = *(const unsigned*)&As[(mb + r + 8) * HST + k0];
                af[mt][2] = *(const unsigned*)&As[(mb + r) * HST     + k0 + 8];
                af[mt][3] = *(const unsigned*)&As[(mb + r + 8) * HST + k0 + 8];
            }
#pragma unroll
            for (int nt = 0; nt < 8; nt++) {
                unsigned b0 = *(const unsigned*)&Bs[(wn + nt * 8 + r) * HST + k0];
                unsigned b1 = *(const unsigned*)&Bs[(wn + nt * 8 + r) * HST + k0 + 8];
#pragma unroll
                for (int mt = 0; mt < 2; mt++)
                    MMA_F16(acc[mt][nt], af[mt][0], af[mt][1], af[mt][2], af[mt][3], b0, b1);
            }
        }
    }

    // epilogue
#pragma unroll
    for (int mt = 0; mt < 2; mt++) {
#pragma unroll
        for (int l2 = 0; l2 < 2; l2++) {
            const int row = by * 128 + wm + mt * 16 + r + 8 * l2;
#pragma unroll
            for (int nt = 0; nt < 8; nt++) {
                const int col = bx * 128 + wn + nt * 8 + 2 * c;
                float v0 = acc[mt][nt][2 * l2 + 0];
                float v1 = acc[mt][nt][2 * l2 + 1];
                if (bias) { v0 += bias[col]; v1 += bias[col + 1]; }
                if (relu) { v0 = fmaxf(v0, 0.f); v1 = fmaxf(v1, 0.f); }
                if (C16) {
                    *(unsigned*)&C16[(size_t)row * N + col] = pack_f16(v0, v1);
                } else {
                    *(float2*)(C + (size_t)row * N + col) = make_float2(v0, v1);
                }
            }
        }
    }
}

extern __shared__ float dynsm[];

__global__ __launch_bounds__(256, 2)
void tgemm16(const u16* __restrict__ A, const u16* __restrict__ Bt,
             float* __restrict__ C, u16* __restrict__ C16, int N, int K,
             const float* __restrict__ bias, int relu)
{
    gemm16_body(A, Bt, C, C16, N, K, bias, relu, blockIdx.x, blockIdx.y, (u16*)dynsm);
}

__global__ __launch_bounds__(256, 2)
void tgemm16_qkv(const u16* __restrict__ A,
                 const u16* __restrict__ Wqt, const u16* __restrict__ Wkt,
                 const u16* __restrict__ Wvt,
                 u16* __restrict__ Q, u16* __restrict__ K, u16* __restrict__ V)
{
    const u16* Bt = (blockIdx.z == 0) ? Wqt : (blockIdx.z == 1) ? Wkt : Wvt;
    u16*       C  = (blockIdx.z == 0) ? Q   : (blockIdx.z == 1) ? K   : V;
    gemm16_body(A, Bt, nullptr, C, D_MODEL, D_MODEL, nullptr, 0,
                blockIdx.x, blockIdx.y, (u16*)dynsm);
}

// ================= weight transpose + fp16 convert: W[K][N] -> Wt[N][K] =========
__global__ __launch_bounds__(256)
void wtrans(const float* __restrict__ W, u16* __restrict__ Wt, int K, int N)
{
    __shared__ float t[32][33];
    const int tid = threadIdx.x;
    const int k0 = blockIdx.y * 32, n0 = blockIdx.x * 32;
    const int r = tid >> 3, c4 = (tid & 7) * 4;

    float4 v = *(const float4*)(W + (size_t)(k0 + r) * N + n0 + c4);
    t[r][c4 + 0] = v.x; t[r][c4 + 1] = v.y; t[r][c4 + 2] = v.z; t[r][c4 + 3] = v.w;
    __syncthreads();

    unsigned o[2];
    o[0] = pack_f16(t[c4 + 0][r], t[c4 + 1][r]);
    o[1] = pack_f16(t[c4 + 2][r], t[c4 + 3][r]);
    *(uint2*)&Wt[(size_t)(n0 + r) * K + k0 + c4] = make_uint2(o[0], o[1]);
}

__global__ __launch_bounds__(256)
void wtrans_qkv(const float* __restrict__ Wq, const float* __restrict__ Wk,
                const float* __restrict__ Wv,
                u16* __restrict__ Wqt, u16* __restrict__ Wkt, u16* __restrict__ Wvt)
{
    __shared__ float t[32][33];
    const float* W = (blockIdx.z == 0) ? Wq : (blockIdx.z == 1) ? Wk : Wv;
    u16*        Wt = (blockIdx.z == 0) ? Wqt : (blockIdx.z == 1) ? Wkt : Wvt;
    const int tid = threadIdx.x;
    const int k0 = blockIdx.y * 32, n0 = blockIdx.x * 32;
    const int r = tid >> 3, c4 = (tid & 7) * 4;

    float4 v = *(const float4*)(W + (size_t)(k0 + r) * D_MODEL + n0 + c4);
    t[r][c4 + 0] = v.x; t[r][c4 + 1] = v.y; t[r][c4 + 2] = v.z; t[r][c4 + 3] = v.w;
    __syncthreads();

    unsigned o[2];
    o[0] = pack_f16(t[c4 + 0][r], t[c4 + 1][r]);
    o[1] = pack_f16(t[c4 + 2][r], t[c4 + 3][r]);
    *(uint2*)&Wt[(size_t)(n0 + r) * D_MODEL + k0 + c4] = make_uint2(o[0], o[1]);
}

// ================= x fp32 -> fp16 ===============================================
__global__ __launch_bounds__(256)
void xconv(const float* __restrict__ x, u16* __restrict__ x16)
{
    const size_t i = ((size_t)blockIdx.x * 256 + threadIdx.x) * 4;
    float4 v = *(const float4*)(x + i);
    *(uint2*)&x16[i] = make_uint2(pack_f16(v.x, v.y), pack_f16(v.z, v.w));
}

// ================= V transpose: g_Vh [b,s][h,d] fp16 -> g_Vt [bh][d][s] =========
__global__ __launch_bounds__(256)
void vtrans(const u16* __restrict__ Vh, u16* __restrict__ Vt)
{
    __shared__ u16 t[64][72];
    const int tid = threadIdx.x;
    const int bh = blockIdx.y, b = bh >> 3, h = bh & 7;
    const int s0 = blockIdx.x * 64;

    const int sr = tid >> 2, sc0 = (tid & 3) * 16;
    const u16* src = Vh + (size_t)(b * SEQ + s0 + sr) * D_MODEL + h * DHEAD + sc0;
    *(uint4*)&t[sr][sc0]     = *(const uint4*)(src);
    *(uint4*)&t[sr][sc0 + 8] = *(const uint4*)(src + 8);
    __syncthreads();

    const int dd = tid >> 2, j0 = (tid & 3) * 2;
    u16* dst = Vt + ((size_t)bh * DHEAD + dd) * SEQ + s0;
#pragma unroll
    for (int jj = 0; jj < 2; jj++) {
        u16 buf[8];
#pragma unroll
        for (int i = 0; i < 8; i++) buf[i] = t[(j0 + jj) * 8 + i][dd];
        *(uint4*)(dst + (j0 + jj) * 8) = *(uint4*)buf;
    }
}

// ================= fused sigmoid-attention, fp16 m16n8k16 =======================
// O[q,:] = sum_k sigmoid(q.k*scale + sbias) * V[k,:]
// CTA: 256 thr (8 warps), q-tile 128 (16 q/warp), k-tile 64, 2 CTAs/SM.
// smem (fp16): Qs[q][d] 128x72 + 2x { Ks[kk][d] 64x72, Vs[d][kk] 64x72 } = 54KB.
#define HS  72
#define KSTG (64*HS)

#define A_ISSUE_KV(kt,s) { \
    const u16* kg = Kp + (baseRow + (size_t)(kt) * 64 + kr) * D_MODEL + colBase + kd0; \
    u16* kd = Ks_ + (s)*KSTG + kr*HS + kd0; \
    cp16(kd, kg); cp16(kd + 8, kg + 8); \
    const u16* vg = Vtp + ((size_t)bh * DHEAD + kr) * SEQ + (size_t)(kt) * 64 + kd0; \
    u16* vd = Vs_ + (s)*KSTG + kr*HS + kd0; \
    cp16(vd, vg); cp16(vd + 8, vg + 8); \
    CP_COMMIT(); }

__global__ __launch_bounds__(256, 2)
void attn_f16(const u16* __restrict__ Qp, const u16* __restrict__ Kp,
              const u16* __restrict__ Vtp, u16* __restrict__ O16,
              float scale, float sbias)
{
    u16* Qs  = (u16*)dynsm;                // 128*72
    u16* Ks_ = Qs + 128 * HS;              // 2 stages of 64*72
    u16* Vs_ = Ks_ + 2 * KSTG;             // 2 stages of 64*72

    const int tid  = threadIdx.x;
    const int warp = tid >> 5;
    const int lane = tid & 31;
    const int r    = lane >> 2;
    const int c    = lane & 3;
    const int q0   = warp * 16;

    const int qt = blockIdx.x;             // 0..31
    const int bh = blockIdx.y;             // 0..15
    const int b  = bh >> 3, h = bh & 7;
    const size_t baseRow = (size_t)b * SEQ;
    const int colBase = h * DHEAD;

    const int kr = tid >> 2, kd0 = (tid & 3) * 16;

    // prologue group 0: Q tile + KV tile 0
    {
        const int qr = tid >> 1, qd0 = (tid & 1) * 32;
        const u16* qg = Qp + (baseRow + (size_t)qt * 128 + qr) * D_MODEL + colBase + qd0;
        u16* qd = Qs + qr * HS + qd0;
#pragma unroll
        for (int i = 0; i < 4; i++) cp16(qd + 8 * i, qg + 8 * i);

        const u16* kg = Kp + (baseRow + (size_t)kr) * D_MODEL + colBase + kd0;
        u16* kd = Ks_ + kr * HS + kd0;
        cp16(kd, kg); cp16(kd + 8, kg + 8);
        const u16* vg = Vtp + ((size_t)bh * DHEAD + kr) * SEQ + kd0;
        u16* vd = Vs_ + kr * HS + kd0;
        cp16(vd, vg); cp16(vd + 8, vg + 8);
        CP_COMMIT();
    }
    // group 1: KV tile 1
    A_ISSUE_KV(1, 1);

    float oacc[8][4];
#pragma unroll
    for (int nt = 0; nt < 8; nt++)
#pragma unroll
        for (int l = 0; l < 4; l++) oacc[nt][l] = 0.f;

    for (int kt = 0; kt < SEQ / 64; kt++) {
        const int s = kt & 1;
        CP_WAIT1();
        __syncthreads();              // stage kt landed

        const u16* Ks = Ks_ + s * KSTG;
        const u16* Vs = Vs_ + s * KSTG;

        // ---- S-phase: S[16q x 64kk] = Q @ K^T ----
        float sacc[8][4];
#pragma unroll
        for (int nt = 0; nt < 8; nt++)
#pragma unroll
            for (int l = 0; l < 4; l++) sacc[nt][l] = 0.f;

#pragma unroll
        for (int j = 0; j < 4; j++) {
            const int d0 = j * 16 + 2 * c;
            unsigned a0 = *(const unsigned*)&Qs[(q0 + r) * HS     + d0];
            unsigned a1 = *(const unsigned*)&Qs[(q0 + r + 8) * HS + d0];
            unsigned a2 = *(const unsigned*)&Qs[(q0 + r) * HS     + d0 + 8];
            unsigned a3 = *(const unsigned*)&Qs[(q0 + r + 8) * HS + d0 + 8];
#pragma unroll
            for (int nt = 0; nt < 8; nt++) {
                unsigned b0 = *(const unsigned*)&Ks[(nt * 8 + r) * HS + d0];
                unsigned b1 = *(const unsigned*)&Ks[(nt * 8 + r) * HS + d0 + 8];
                MMA_F16(sacc[nt], a0, a1, a2, a3, b0, b1);
            }
        }

        // sigmoid(x) = t - t^2, t = exp(x); valid since x <= ~-7 here
#pragma unroll
        for (int nt = 0; nt < 8; nt++)
#pragma unroll
            for (int l = 0; l < 4; l++) {
                float xv = fmaf(sacc[nt][l], scale, sbias);
                float t  = __expf(xv);
                sacc[nt][l] = fmaf(-t, t, t);
            }

        // ---- O-phase: O[16q x 64d] += S @ V; A-frag = packed C-frag pairs ----
#pragma unroll
        for (int j = 0; j < 4; j++) {
            unsigned a0 = pack_f16(sacc[2 * j][0],     sacc[2 * j][1]);
            unsigned a1 = pack_f16(sacc[2 * j][2],     sacc[2 * j][3]);
            unsigned a2 = pack_f16(sacc[2 * j + 1][0], sacc[2 * j + 1][1]);
            unsigned a3 = pack_f16(sacc[2 * j + 1][2], sacc[2 * j + 1][3]);
            const int k0 = j * 16 + 2 * c;
#pragma unroll
            for (int nt = 0; nt < 8; nt++) {
                unsigned b0 = *(const unsigned*)&Vs[(nt * 8 + r) * HS + k0];
                unsigned b1 = *(const unsigned*)&Vs[(nt * 8 + r) * HS + k0 + 8];
                MMA_F16(oacc[nt], a0, a1, a2, a3, b0, b1);
            }
        }

        __syncthreads();              // all warps done with stage s
        if (kt + 2 < SEQ / 64) A_ISSUE_KV(kt + 2, s);
    }

    // write O tile (fp16)
#pragma unroll
    for (int l2 = 0; l2 < 2; l2++) {
        const size_t row = baseRow + (size_t)qt * 128 + q0 + r + 8 * l2;
#pragma unroll
        for (int nt = 0; nt < 8; nt++) {
            const int col = colBase + nt * 8 + 2 * c;
            *(unsigned*)&O16[row * D_MODEL + col] =
                pack_f16(oacc[nt][2 * l2 + 0], oacc[nt][2 * l2 + 1]);
        }
    }
}

// ---------------- residual + layernorm over 512 cols (optional fp16 copy) ------
__global__ __launch_bounds__(128)
void ln_res_kernel(const float* __restrict__ a, const float* __restrict__ t,
                   const float* __restrict__ gamma, const float* __restrict__ beta,
                   float* __restrict__ out, u16* __restrict__ out16)
{
    const int row = blockIdx.x;
    const int tid = threadIdx.x;      // 128 threads * 4 = 512
    const float4 va = ((const float4*)(a + (size_t)row * D_MODEL))[tid];
    const float4 vt = ((const float4*)(t + (size_t)row * D_MODEL))[tid];
    float v0 = va.x + vt.x, v1 = va.y + vt.y, v2 = va.z + vt.z, v3 = va.w + vt.w;

    float s  = v0 + v1 + v2 + v3;
    float ss = v0 * v0 + v1 * v1 + v2 * v2 + v3 * v3;
#pragma unroll
    for (int o = 16; o; o >>= 1) {
        s  += __shfl_xor_sync(0xffffffffu, s,  o);
        ss += __shfl_xor_sync(0xffffffffu, ss, o);
    }
    __shared__ float sh[8];
    if ((tid & 31) == 0) { sh[tid >> 5] = s; sh[4 + (tid >> 5)] = ss; }
    __syncthreads();
    float S2  = sh[0] + sh[1] + sh[2] + sh[3];
    float SS2 = sh[4] + sh[5] + sh[6] + sh[7];

    const float mu   = S2 * (1.f / 512.f);
    const float var  = SS2 * (1.f / 512.f) - mu * mu;
    const float rstd = rsqrtf(var + 1e-5f);

    const float4 g  = ((const float4*)gamma)[tid];
    const float4 bb = ((const float4*)beta)[tid];
    float4 o;
    o.x = (v0 - mu) * rstd * g.x + bb.x;
    o.y = (v1 - mu) * rstd * g.y + bb.y;
    o.z = (v2 - mu) * rstd * g.z + bb.z;
    o.w = (v3 - mu) * rstd * g.w + bb.w;
    ((float4*)(out + (size_t)row * D_MODEL))[tid] = o;
    if (out16) {
        *(uint2*)&out16[(size_t)row * D_MODEL + tid * 4] =
            make_uint2(pack_f16(o.x, o.y), pack_f16(o.z, o.w));
    }
}

// ---------------- launch --------------------------------------------------------
extern "C" void kernel_launch(void* const* d_in, const int* in_sizes, int n_in,
                              void* d_out, int out_size)
{
    const float* x       = (const float*)d_in[0];
    const float* Wq      = (const float*)d_in[1];
    const float* Wk      = (const float*)d_in[2];
    const float* Wv      = (const float*)d_in[3];
    const float* dense_w = (const float*)d_in[4];
    const float* dense_b = (const float*)d_in[5];
    const float* ff1_w   = (const float*)d_in[6];
    const float* ff1_b   = (const float*)d_in[7];
    const float* ff2_w   = (const float*)d_in[8];
    const float* ff2_b   = (const float*)d_in[9];
    const float* ln1_g   = (const float*)d_in[10];
    const float* ln1_b   = (const float*)d_in[11];
    const float* ln2_g   = (const float*)d_in[12];
    const float* ln2_b   = (const float*)d_in[13];

    u16 *x16, *Wqt, *Wkt, *Wvt, *Wdt, *W1t, *W2t;
    u16 *Qh, *Kh, *Vh, *Vt, *O16, *X1h, *F16;
    float *T, *X1;
    cudaGetSymbolAddress((void**)&x16, g_x16);
    cudaGetSymbolAddress((void**)&Wqt, g_Wqt);
    cudaGetSymbolAddress((void**)&Wkt, g_Wkt);
    cudaGetSymbolAddress((void**)&Wvt, g_Wvt);
    cudaGetSymbolAddress((void**)&Wdt, g_Wdt);
    cudaGetSymbolAddress((void**)&W1t, g_W1t);
    cudaGetSymbolAddress((void**)&W2t, g_W2t);
    cudaGetSymbolAddress((void**)&Qh,  g_Qh);
    cudaGetSymbolAddress((void**)&Kh,  g_Kh);
    cudaGetSymbolAddress((void**)&Vh,  g_Vh);
    cudaGetSymbolAddress((void**)&Vt,  g_Vt);
    cudaGetSymbolAddress((void**)&O16, g_O16);
    cudaGetSymbolAddress((void**)&X1h, g_X1h);
    cudaGetSymbolAddress((void**)&F16, g_F16);
    cudaGetSymbolAddress((void**)&T,   g_T);
    cudaGetSymbolAddress((void**)&X1,  g_X1);

    const int gemm_smem = 6 * HSTG * 2;               // 61440 B
    const int attn_smem = (128 * HS + 4 * KSTG) * 2;  // 55296 B
    cudaFuncSetAttribute(tgemm16,     cudaFuncAttributeMaxDynamicSharedMemorySize, gemm_smem);
    cudaFuncSetAttribute(tgemm16_qkv, cudaFuncAttributeMaxDynamicSharedMemorySize, gemm_smem);
    cudaFuncSetAttribute(attn_f16,    cudaFuncAttributeMaxDynamicSharedMemorySize, attn_smem);

    dim3 blk(256);

    // precompute: fp16 x, fp16 transposed weights
    xconv<<<MROWS * D_MODEL / 1024, blk>>>(x, x16);
    wtrans_qkv<<<dim3(D_MODEL / 32, D_MODEL / 32, 3), blk>>>(Wq, Wk, Wv, Wqt, Wkt, Wvt);
    wtrans<<<dim3(D_MODEL / 32, D_MODEL / 32), blk>>>(dense_w, Wdt, D_MODEL, D_MODEL);
    wtrans<<<dim3(DFF / 32, D_MODEL / 32), blk>>>(ff1_w, W1t, D_MODEL, DFF);
    wtrans<<<dim3(D_MODEL / 32, DFF / 32), blk>>>(ff2_w, W2t, DFF, D_MODEL);

    // Q,K,V projections (fp16)
    tgemm16_qkv<<<dim3(D_MODEL / 128, MROWS / 128, 3), blk, gemm_smem>>>(
        x16, Wqt, Wkt, Wvt, Qh, Kh, Vh);

    // V transpose to [bh][d][s]
    vtrans<<<dim3(SEQ / 64, BATCH * NHEAD), blk>>>(Vh, Vt);

    // fused sigmoid attention (fp16)
    attn_f16<<<dim3(SEQ / 128, BATCH * NHEAD), blk, attn_smem>>>(
        Qh, Kh, Vt, O16, 0.125f, -8.317766166719343f);  // 1/sqrt(64), -log(4096)

    // dense + residual LN1 (X1 fp32 + fp16 copy)
    tgemm16<<<dim3(D_MODEL / 128, MROWS / 128), blk, gemm_smem>>>(
        O16, Wdt, T, nullptr, D_MODEL, D_MODEL, dense_b, 0);
    ln_res_kernel<<<MROWS, 128>>>(x, T, ln1_g, ln1_b, X1, X1h);

    // FFN + residual LN2
    tgemm16<<<dim3(DFF / 128, MROWS / 128), blk, gemm_smem>>>(
        X1h, W1t, nullptr, F16, DFF, D_MODEL, ff1_b, 1);
    tgemm16<<<dim3(D_MODEL / 128, MROWS / 128), blk, gemm_smem>>>(
        F16, W2t, T, nullptr, D_MODEL, DFF, ff2_b, 0);
    ln_res_kernel<<<MROWS, 128>>>(X1, T, ln2_g, ln2_b, (float*)d_out, nullptr);
}